// round 1
// baseline (speedup 1.0000x reference)
#include <cuda_runtime.h>
#include <math.h>

// ---------------- Problem constants ----------------
constexpr int B_    = 16;
constexpr int N_    = 4096;
constexpr int LD    = 256;
constexpr int H_    = 8;
constexpr int DH    = 64;
constexpr int WW    = 128;
constexpr int INNER = 512;   // H_*DH
constexpr int DEPTH = 4;
constexpr int FF    = 1024;
constexpr int SLACK = 50;
constexpr int R_    = B_ * N_;          // 65536 rows
constexpr int QKVW  = 3 * INNER;        // 1536

// ---------------- Scratch (static device memory; no allocs allowed) ----------------
__device__ float g_h[(size_t)R_ * LD];          // 64 MB residual stream
__device__ float g_y[(size_t)R_ * LD];          // 64 MB LN output
__device__ float g_qkv[(size_t)R_ * QKVW];      // 384 MB
__device__ float g_o[(size_t)R_ * INNER];       // 128 MB attention output
__device__ float g_ff[(size_t)R_ * FF];         // 256 MB FF hidden
__device__ float g_cos[(size_t)N_ * 32];        // RoPE tables
__device__ float g_sin[(size_t)N_ * 32];

// ---------------- RoPE table: fp32-emulated angle, accurate reduction ----------------
__global__ void rope_table_kernel() {
    int idx = blockIdx.x * blockDim.x + threadIdx.x;  // N_*32
    if (idx >= N_ * 32) return;
    int n = idx >> 5, d = idx & 31;
    // inv_freq computed like fp32: 1/10000^(2d/64), rounded to float
    float invf = (float)(1.0 / pow(10000.0, (double)(2 * d) / 64.0));
    float angf = (float)n * invf;                 // fp32 product (matches reference dataflow)
    double a = (double)angf;                      // accurate sin/cos of that fp32 value
    g_cos[idx] = (float)cos(a);
    g_sin[idx] = (float)sin(a);
}

// ---------------- Expand: h = x @ W_exp + b_exp + pos_emb ----------------
__global__ void expand_kernel(const float* __restrict__ x, const float* __restrict__ We,
                              const float* __restrict__ be, const float* __restrict__ pe) {
    int row = blockIdx.x;
    int c   = threadIdx.x;
    int n   = row & (N_ - 1);
    float x0 = x[row * 2 + 0], x1 = x[row * 2 + 1];
    g_h[(size_t)row * LD + c] = x0 * We[c] + x1 * We[LD + c] + be[c] + pe[n * LD + c];
}

// ---------------- LayerNorm (one block of 256 per row) ----------------
__global__ void ln_kernel(const float* __restrict__ src, float* __restrict__ dst,
                          const float* __restrict__ gg, const float* __restrict__ bb) {
    int row = blockIdx.x, c = threadIdx.x;
    float v = src[(size_t)row * LD + c];
    float s = v, sq = v * v;
    #pragma unroll
    for (int o = 16; o > 0; o >>= 1) {
        s  += __shfl_down_sync(0xffffffffu, s, o);
        sq += __shfl_down_sync(0xffffffffu, sq, o);
    }
    __shared__ float sh[16];
    __shared__ float stat[2];
    if ((c & 31) == 0) { sh[c >> 5] = s; sh[8 + (c >> 5)] = sq; }
    __syncthreads();
    if (c == 0) {
        float S = 0.f, SQ = 0.f;
        #pragma unroll
        for (int i = 0; i < 8; i++) { S += sh[i]; SQ += sh[8 + i]; }
        float mean = S * (1.f / LD);
        stat[0] = mean;
        stat[1] = rsqrtf(SQ * (1.f / LD) - mean * mean + 1e-5f);
    }
    __syncthreads();
    dst[(size_t)row * LD + c] = (v - stat[0]) * stat[1] * gg[c] + bb[c];
}

// ---------------- SGEMM 128x128x8, 8x8 per thread, templated epilogue ----------------
// EPI: 0 = store, 1 = +bias then exact GELU, 2 = C += AB, 3 = C += AB + bias
template <int EPI>
__global__ __launch_bounds__(256)
void sgemm128(const float* __restrict__ A, const float* __restrict__ Bm,
              float* __restrict__ C, const float* __restrict__ bias,
              int M, int Nc, int K) {
    __shared__ float As[8][128];
    __shared__ float Bs[8][128];
    int tid  = threadIdx.x;
    int row0 = blockIdx.y * 128;
    int col0 = blockIdx.x * 128;
    int tr   = (tid >> 4) * 8;
    int tc   = (tid & 15) * 8;
    int arow = tid >> 1;
    int ak   = (tid & 1) * 4;
    int brow = tid >> 5;
    int bcol = (tid & 31) * 4;

    float acc[8][8];
    #pragma unroll
    for (int i = 0; i < 8; i++)
        #pragma unroll
        for (int j = 0; j < 8; j++) acc[i][j] = 0.f;

    const float* Aptr = A + (size_t)(row0 + arow) * K + ak;
    const float* Bptr = Bm + (size_t)brow * Nc + col0 + bcol;

    for (int kt = 0; kt < K; kt += 8) {
        float4 av = *(const float4*)(Aptr + kt);
        float4 bv = *(const float4*)(Bptr + (size_t)kt * Nc);
        As[ak + 0][arow] = av.x;
        As[ak + 1][arow] = av.y;
        As[ak + 2][arow] = av.z;
        As[ak + 3][arow] = av.w;
        *(float4*)&Bs[brow][bcol] = bv;
        __syncthreads();
        #pragma unroll
        for (int kk = 0; kk < 8; ++kk) {
            float4 a0 = *(const float4*)&As[kk][tr];
            float4 a1 = *(const float4*)&As[kk][tr + 4];
            float4 b0 = *(const float4*)&Bs[kk][tc];
            float4 b1 = *(const float4*)&Bs[kk][tc + 4];
            float a[8] = {a0.x, a0.y, a0.z, a0.w, a1.x, a1.y, a1.z, a1.w};
            float b[8] = {b0.x, b0.y, b0.z, b0.w, b1.x, b1.y, b1.z, b1.w};
            #pragma unroll
            for (int i = 0; i < 8; i++)
                #pragma unroll
                for (int j = 0; j < 8; j++)
                    acc[i][j] = fmaf(a[i], b[j], acc[i][j]);
        }
        __syncthreads();
    }

    #pragma unroll
    for (int i = 0; i < 8; i++) {
        size_t off = (size_t)(row0 + tr + i) * Nc + col0 + tc;
        #pragma unroll
        for (int j = 0; j < 8; j++) {
            float v = acc[i][j];
            if (EPI == 0) {
                C[off + j] = v;
            } else if (EPI == 1) {
                v += bias[col0 + tc + j];
                C[off + j] = 0.5f * v * (1.f + erff(v * 0.70710678118654752f));
            } else if (EPI == 2) {
                C[off + j] += v;
            } else {
                v += bias[col0 + tc + j];
                C[off + j] += v;
            }
        }
    }
}

// ---------------- Fused local attention (rotary + flash softmax) ----------------
// grid (N/W, H, B), 128 threads = one query row each. smem: K,V tiles 256x64 padded.
constexpr int KSTRIDE = 68;  // 64 + 4 pad: 16B-aligned rows, conflict-free strided access

__global__ __launch_bounds__(128)
void attn_kernel(const float* __restrict__ qkv, float* __restrict__ outp) {
    extern __shared__ float sm[];
    float* ks = sm;
    float* vs = sm + 256 * KSTRIDE;

    int w = blockIdx.x, head = blockIdx.y, b = blockIdx.z;
    int t = threadIdx.x;
    int qbase = w * WW;
    size_t rowbase = (size_t)b * N_;

    // Load K tile (2 windows back..current) with rotary applied at key positions.
    for (int idx = t; idx < 256 * 8; idx += 128) {
        int jj = idx >> 3;
        int d0 = (idx & 7) * 4;           // 0..28
        int p  = qbase - WW + jj;
        float4 lo = {0, 0, 0, 0}, hi = {0, 0, 0, 0};
        float4 olo = {0, 0, 0, 0}, ohi = {0, 0, 0, 0};
        if (p >= 0) {
            const float* kp = qkv + (rowbase + p) * QKVW + INNER + head * DH;
            lo = *(const float4*)(kp + d0);
            hi = *(const float4*)(kp + d0 + 32);
            #pragma unroll
            for (int u = 0; u < 4; ++u) {
                int d = d0 + u;
                float cs = g_cos[p * 32 + d];
                float sn = g_sin[p * 32 + d];
                float a  = (&lo.x)[u], b2 = (&hi.x)[u];
                (&olo.x)[u] = a * cs - b2 * sn;
                (&ohi.x)[u] = b2 * cs + a * sn;
            }
        }
        *(float4*)&ks[jj * KSTRIDE + d0]      = olo;
        *(float4*)&ks[jj * KSTRIDE + d0 + 32] = ohi;
    }
    // Load V tile (no rotary)
    for (int idx = t; idx < 256 * 16; idx += 128) {
        int jj = idx >> 4;
        int c4 = (idx & 15) * 4;
        int p  = qbase - WW + jj;
        float4 v4 = {0, 0, 0, 0};
        if (p >= 0)
            v4 = *(const float4*)(qkv + (rowbase + p) * QKVW + 2 * INNER + head * DH + c4);
        *(float4*)&vs[jj * KSTRIDE + c4] = v4;
    }

    // Per-thread query row, rotary + scale
    int i = qbase + t;
    float q[64];
    {
        const float* qp = qkv + (rowbase + i) * QKVW + head * DH;
        #pragma unroll
        for (int d = 0; d < 32; ++d) {
            float cs = g_cos[i * 32 + d];
            float sn = g_sin[i * 32 + d];
            float a = qp[d], b2 = qp[d + 32];
            q[d]      = (a * cs - b2 * sn) * 0.125f;
            q[d + 32] = (b2 * cs + a * sn) * 0.125f;
        }
    }
    __syncthreads();

    float o[64];
    #pragma unroll
    for (int d = 0; d < 64; ++d) o[d] = 0.f;
    float m = -1e30f, l = 0.f;

    // Legal keys for query i: j in [max(0, i-128), i]  <=>  jj in [t, t+128] (and jj>=128 if w==0)
    int rstart = (w == 0) ? (WW - t) : 0;
    for (int r = rstart; r <= WW; ++r) {
        int jj = t + r;
        const float* kr = &ks[jj * KSTRIDE];
        float s = 0.f;
        #pragma unroll
        for (int d4 = 0; d4 < 64; d4 += 4) {
            float4 k4 = *(const float4*)(kr + d4);
            s = fmaf(q[d4 + 0], k4.x, s);
            s = fmaf(q[d4 + 1], k4.y, s);
            s = fmaf(q[d4 + 2], k4.z, s);
            s = fmaf(q[d4 + 3], k4.w, s);
        }
        float mn   = fmaxf(m, s);
        float corr = __expf(m - mn);
        float pp   = __expf(s - mn);
        l = l * corr + pp;
        m = mn;
        const float* vr = &vs[jj * KSTRIDE];
        #pragma unroll
        for (int d4 = 0; d4 < 64; d4 += 4) {
            float4 v4 = *(const float4*)(vr + d4);
            o[d4 + 0] = fmaf(pp, v4.x, o[d4 + 0] * corr);
            o[d4 + 1] = fmaf(pp, v4.y, o[d4 + 1] * corr);
            o[d4 + 2] = fmaf(pp, v4.z, o[d4 + 2] * corr);
            o[d4 + 3] = fmaf(pp, v4.w, o[d4 + 3] * corr);
        }
    }

    float inv = 1.f / l;
    float* op = outp + (rowbase + i) * INNER + head * DH;
    #pragma unroll
    for (int d4 = 0; d4 < 64; d4 += 4) {
        float4 r4 = {o[d4] * inv, o[d4 + 1] * inv, o[d4 + 2] * inv, o[d4 + 3] * inv};
        *(float4*)(op + d4) = r4;
    }
}

// ---------------- Final LN + logits + slice ----------------
__global__ void final_kernel(const float* __restrict__ gg, const float* __restrict__ bb,
                             const float* __restrict__ wl, float* __restrict__ out) {
    int row = blockIdx.x, c = threadIdx.x;
    int n = row & (N_ - 1);
    if (n < SLACK || n >= N_ - SLACK) return;   // whole block uniform: safe
    float v = g_h[(size_t)row * LD + c];
    __shared__ float sh[16];
    __shared__ float stat[2];
    float s = v, sq = v * v;
    #pragma unroll
    for (int o = 16; o > 0; o >>= 1) {
        s  += __shfl_down_sync(0xffffffffu, s, o);
        sq += __shfl_down_sync(0xffffffffu, sq, o);
    }
    if ((c & 31) == 0) { sh[c >> 5] = s; sh[8 + (c >> 5)] = sq; }
    __syncthreads();
    if (c == 0) {
        float S = 0.f, SQ = 0.f;
        #pragma unroll
        for (int i = 0; i < 8; i++) { S += sh[i]; SQ += sh[8 + i]; }
        float mean = S * (1.f / LD);
        stat[0] = mean;
        stat[1] = rsqrtf(SQ * (1.f / LD) - mean * mean + 1e-5f);
    }
    __syncthreads();
    float contrib = ((v - stat[0]) * stat[1] * gg[c] + bb[c]) * wl[c];
    #pragma unroll
    for (int o = 16; o > 0; o >>= 1)
        contrib += __shfl_down_sync(0xffffffffu, contrib, o);
    __syncthreads();
    if ((c & 31) == 0) sh[c >> 5] = contrib;
    __syncthreads();
    if (c == 0) {
        float T = 0.f;
        #pragma unroll
        for (int i = 0; i < 8; i++) T += sh[i];
        int bidx = row >> 12;  // row / N_
        out[bidx * (N_ - 2 * SLACK) + (n - SLACK)] = T;
    }
}

// ---------------- Launch ----------------
extern "C" void kernel_launch(void* const* d_in, const int* in_sizes, int n_in,
                              void* d_out, int out_size) {
    const float* x        = (const float*)d_in[0];
    const float* W_exp    = (const float*)d_in[1];
    const float* b_exp    = (const float*)d_in[2];
    const float* pos_emb  = (const float*)d_in[3];
    const float* ln_att_g = (const float*)d_in[4];
    const float* ln_att_b = (const float*)d_in[5];
    const float* Wqkv     = (const float*)d_in[6];
    const float* Wout     = (const float*)d_in[7];
    const float* ln_ff_g  = (const float*)d_in[8];
    const float* ln_ff_b  = (const float*)d_in[9];
    const float* W1       = (const float*)d_in[10];
    const float* b1       = (const float*)d_in[11];
    const float* W2       = (const float*)d_in[12];
    const float* b2       = (const float*)d_in[13];
    const float* ln_f_g   = (const float*)d_in[14];
    const float* ln_f_b   = (const float*)d_in[15];
    const float* W_logits = (const float*)d_in[16];
    float* out = (float*)d_out;

    float *ph, *py, *pqkv, *po, *pff;
    cudaGetSymbolAddress((void**)&ph,   g_h);
    cudaGetSymbolAddress((void**)&py,   g_y);
    cudaGetSymbolAddress((void**)&pqkv, g_qkv);
    cudaGetSymbolAddress((void**)&po,   g_o);
    cudaGetSymbolAddress((void**)&pff,  g_ff);

    int smem_attn = 2 * 256 * KSTRIDE * (int)sizeof(float);  // 139264 B
    cudaFuncSetAttribute(attn_kernel, cudaFuncAttributeMaxDynamicSharedMemorySize, smem_attn);

    rope_table_kernel<<<(N_ * 32 + 255) / 256, 256>>>();
    expand_kernel<<<R_, LD>>>(x, W_exp, b_exp, pos_emb);

    for (int l = 0; l < DEPTH; ++l) {
        ln_kernel<<<R_, LD>>>(ph, py, ln_att_g + l * LD, ln_att_b + l * LD);
        sgemm128<0><<<dim3(QKVW / 128, R_ / 128), 256>>>(
            py, Wqkv + (size_t)l * LD * QKVW, pqkv, nullptr, R_, QKVW, LD);
        attn_kernel<<<dim3(N_ / WW, H_, B_), 128, smem_attn>>>(pqkv, po);
        sgemm128<2><<<dim3(LD / 128, R_ / 128), 256>>>(
            po, Wout + (size_t)l * INNER * LD, ph, nullptr, R_, LD, INNER);
        ln_kernel<<<R_, LD>>>(ph, py, ln_ff_g + l * LD, ln_ff_b + l * LD);
        sgemm128<1><<<dim3(FF / 128, R_ / 128), 256>>>(
            py, W1 + (size_t)l * LD * FF, pff, b1 + (size_t)l * FF, R_, FF, LD);
        sgemm128<3><<<dim3(LD / 128, R_ / 128), 256>>>(
            pff, W2 + (size_t)l * FF * LD, ph, b2 + (size_t)l * LD, R_, LD, FF);
    }

    final_kernel<<<R_, LD>>>(ln_f_g, ln_f_b, W_logits, out);
}

// round 2
// speedup vs baseline: 1.5217x; 1.5217x over previous
#include <cuda_runtime.h>
#include <math.h>

// ---------------- Problem constants ----------------
constexpr int B_    = 16;
constexpr int N_    = 4096;
constexpr int LD    = 256;
constexpr int H_    = 8;
constexpr int DH    = 64;
constexpr int WW    = 128;
constexpr int INNER = 512;   // H_*DH
constexpr int DEPTH = 4;
constexpr int FF    = 1024;
constexpr int SLACK = 50;
constexpr int R_    = B_ * N_;          // 65536 rows
constexpr int QKVW  = 3 * INNER;        // 1536

// ---------------- Scratch (static device memory; no allocs allowed) ----------------
__device__ float g_h[(size_t)R_ * LD];          // 64 MB residual stream
__device__ float g_y[(size_t)R_ * LD];          // 64 MB LN output
__device__ float g_qkv[(size_t)R_ * QKVW];      // 384 MB
__device__ float g_o[(size_t)R_ * INNER];       // 128 MB attention output
__device__ float g_ff[(size_t)R_ * FF];         // 256 MB FF hidden
__device__ float g_cos[(size_t)N_ * 32];        // RoPE tables
__device__ float g_sin[(size_t)N_ * 32];

// ---------------- RoPE table ----------------
__global__ void rope_table_kernel() {
    int idx = blockIdx.x * blockDim.x + threadIdx.x;  // N_*32
    if (idx >= N_ * 32) return;
    int n = idx >> 5, d = idx & 31;
    float invf = (float)(1.0 / pow(10000.0, (double)(2 * d) / 64.0));
    float angf = (float)n * invf;
    double a = (double)angf;
    g_cos[idx] = (float)cos(a);
    g_sin[idx] = (float)sin(a);
}

// ---------------- Expand: h = x @ W_exp + b_exp + pos_emb ----------------
__global__ void expand_kernel(const float* __restrict__ x, const float* __restrict__ We,
                              const float* __restrict__ be, const float* __restrict__ pe) {
    int row = blockIdx.x;
    int c   = threadIdx.x;
    int n   = row & (N_ - 1);
    float x0 = x[row * 2 + 0], x1 = x[row * 2 + 1];
    g_h[(size_t)row * LD + c] = x0 * We[c] + x1 * We[LD + c] + be[c] + pe[n * LD + c];
}

// ---------------- LayerNorm ----------------
__global__ void ln_kernel(const float* __restrict__ src, float* __restrict__ dst,
                          const float* __restrict__ gg, const float* __restrict__ bb) {
    int row = blockIdx.x, c = threadIdx.x;
    float v = src[(size_t)row * LD + c];
    float s = v, sq = v * v;
    #pragma unroll
    for (int o = 16; o > 0; o >>= 1) {
        s  += __shfl_down_sync(0xffffffffu, s, o);
        sq += __shfl_down_sync(0xffffffffu, sq, o);
    }
    __shared__ float sh[16];
    __shared__ float stat[2];
    if ((c & 31) == 0) { sh[c >> 5] = s; sh[8 + (c >> 5)] = sq; }
    __syncthreads();
    if (c == 0) {
        float S = 0.f, SQ = 0.f;
        #pragma unroll
        for (int i = 0; i < 8; i++) { S += sh[i]; SQ += sh[8 + i]; }
        float mean = S * (1.f / LD);
        stat[0] = mean;
        stat[1] = rsqrtf(SQ * (1.f / LD) - mean * mean + 1e-5f);
    }
    __syncthreads();
    dst[(size_t)row * LD + c] = (v - stat[0]) * stat[1] * gg[c] + bb[c];
}

// ---------------- TF32 tensor-core GEMM ----------------
// 128x128 block, BK=16, 8 warps (2x4), warp tile 64x32, m16n8k8 TF32 MMA.
// A staged in smem K-permuted so a thread's A fragment (both k-steps) is one LDS.128.
// B staged k-major (rows = permuted k), vectorized conflict-free store, broadcast LDS.32 reads.
// EPI: 0 = store, 1 = +bias then exact GELU, 2 = C += AB, 3 = C += AB + bias

__device__ __forceinline__ unsigned f2tf(float x) {
    unsigned u;
    asm("cvt.rna.tf32.f32 %0, %1;" : "=r"(u) : "f"(x));
    return u;
}

__device__ __forceinline__ void mma_tf32(float* c, unsigned a0, unsigned a1,
                                         unsigned a2, unsigned a3,
                                         unsigned b0, unsigned b1) {
    asm volatile("mma.sync.aligned.m16n8k8.row.col.f32.tf32.tf32.f32 "
                 "{%0,%1,%2,%3}, {%4,%5,%6,%7}, {%8,%9}, {%0,%1,%2,%3};\n"
                 : "+f"(c[0]), "+f"(c[1]), "+f"(c[2]), "+f"(c[3])
                 : "r"(a0), "r"(a1), "r"(a2), "r"(a3), "r"(b0), "r"(b1));
}

constexpr int AS_STRIDE = 20;   // 16 + 4 pad
constexpr int BS_STRIDE = 132;  // 128 + 4 pad

template <int EPI>
__global__ __launch_bounds__(256, 2)
void tgemm(const float* __restrict__ A, const float* __restrict__ Bm,
           float* __restrict__ C, const float* __restrict__ bias,
           int M, int Nc, int K) {
    __shared__ float As[128][AS_STRIDE];
    __shared__ float Bs[16][BS_STRIDE];

    int tid  = threadIdx.x;
    int row0 = blockIdx.y * 128;
    int col0 = blockIdx.x * 128;
    int lane = tid & 31, w = tid >> 5;
    int gid  = lane >> 2, tig = lane & 3;
    int wr   = w & 1;        // 2 warps in M (64 rows each)
    int wc   = w >> 1;       // 4 warps in N (32 cols each)

    // staging indices
    int ar = tid >> 2;       // 0..63 (A row within tile; +64 for 2nd half)
    int aj = tid & 3;        // which k-quad (k = 4*aj + u)
    int bk = tid >> 5;       // 0..7 (B k within tile; +8 for 2nd half)
    int bc = tid & 31;       // n-quad
    int s0 = ((bk & 3) << 2) | (bk >> 2);       // s(bk)
    int s1 = s0 + 2;                            // s(bk+8)

    float acc[4][4][4];
    #pragma unroll
    for (int mi = 0; mi < 4; mi++)
        #pragma unroll
        for (int ni = 0; ni < 4; ni++)
            #pragma unroll
            for (int e = 0; e < 4; e++) acc[mi][ni][e] = 0.f;

    const float* Ap0 = A + (size_t)(row0 + ar) * K + aj * 4;
    const float* Ap1 = Ap0 + (size_t)64 * K;
    const float* Bp0 = Bm + (size_t)bk * Nc + col0 + bc * 4;
    const float* Bp1 = Bp0 + (size_t)8 * Nc;

    float4 aR0 = *(const float4*)(Ap0);
    float4 aR1 = *(const float4*)(Ap1);
    float4 bR0 = *(const float4*)(Bp0);
    float4 bR1 = *(const float4*)(Bp1);

    for (int kt = 0; kt < K; kt += 16) {
        // ---- stage with tf32 rounding (K-permuted layout) ----
        As[ar][aj]           = __uint_as_float(f2tf(aR0.x));
        As[ar][aj + 4]       = __uint_as_float(f2tf(aR0.y));
        As[ar][aj + 8]       = __uint_as_float(f2tf(aR0.z));
        As[ar][aj + 12]      = __uint_as_float(f2tf(aR0.w));
        As[ar + 64][aj]      = __uint_as_float(f2tf(aR1.x));
        As[ar + 64][aj + 4]  = __uint_as_float(f2tf(aR1.y));
        As[ar + 64][aj + 8]  = __uint_as_float(f2tf(aR1.z));
        As[ar + 64][aj + 12] = __uint_as_float(f2tf(aR1.w));
        {
            float4 t0, t1;
            t0.x = __uint_as_float(f2tf(bR0.x)); t0.y = __uint_as_float(f2tf(bR0.y));
            t0.z = __uint_as_float(f2tf(bR0.z)); t0.w = __uint_as_float(f2tf(bR0.w));
            t1.x = __uint_as_float(f2tf(bR1.x)); t1.y = __uint_as_float(f2tf(bR1.y));
            t1.z = __uint_as_float(f2tf(bR1.z)); t1.w = __uint_as_float(f2tf(bR1.w));
            *(float4*)&Bs[s0][bc * 4] = t0;
            *(float4*)&Bs[s1][bc * 4] = t1;
        }
        __syncthreads();

        // ---- prefetch next tile ----
        if (kt + 16 < K) {
            aR0 = *(const float4*)(Ap0 + kt + 16);
            aR1 = *(const float4*)(Ap1 + kt + 16);
            bR0 = *(const float4*)(Bp0 + (size_t)(kt + 16) * Nc);
            bR1 = *(const float4*)(Bp1 + (size_t)(kt + 16) * Nc);
        }

        // ---- A fragments: one LDS.128 covers k = {tig, tig+4, tig+8, tig+12} ----
        float4 fA[4][2];
        #pragma unroll
        for (int mi = 0; mi < 4; mi++) {
            int m = wr * 64 + mi * 16 + gid;
            fA[mi][0] = *(const float4*)&As[m][tig * 4];
            fA[mi][1] = *(const float4*)&As[m + 8][tig * 4];
        }

        // ---- B fragments + MMA ----
        #pragma unroll
        for (int ni = 0; ni < 4; ni++) {
            int n = wc * 32 + ni * 8 + gid;
            unsigned b00 = __float_as_uint(Bs[tig * 4 + 0][n]);
            unsigned b01 = __float_as_uint(Bs[tig * 4 + 1][n]);
            unsigned b10 = __float_as_uint(Bs[tig * 4 + 2][n]);
            unsigned b11 = __float_as_uint(Bs[tig * 4 + 3][n]);
            #pragma unroll
            for (int mi = 0; mi < 4; mi++) {
                mma_tf32(acc[mi][ni],
                         __float_as_uint(fA[mi][0].x), __float_as_uint(fA[mi][1].x),
                         __float_as_uint(fA[mi][0].y), __float_as_uint(fA[mi][1].y),
                         b00, b01);
                mma_tf32(acc[mi][ni],
                         __float_as_uint(fA[mi][0].z), __float_as_uint(fA[mi][1].z),
                         __float_as_uint(fA[mi][0].w), __float_as_uint(fA[mi][1].w),
                         b10, b11);
            }
        }
        __syncthreads();
    }

    // ---- epilogue ----
    #pragma unroll
    for (int mi = 0; mi < 4; mi++) {
        int ra = row0 + wr * 64 + mi * 16 + gid;
        #pragma unroll
        for (int ni = 0; ni < 4; ni++) {
            int cc = col0 + wc * 32 + ni * 8 + tig * 2;
            #pragma unroll
            for (int half = 0; half < 2; half++) {
                int r = ra + half * 8;
                float v0 = acc[mi][ni][half * 2 + 0];
                float v1 = acc[mi][ni][half * 2 + 1];
                size_t off = (size_t)r * Nc + cc;
                if (EPI == 0) {
                    C[off]     = v0;
                    C[off + 1] = v1;
                } else if (EPI == 1) {
                    v0 += bias[cc];
                    v1 += bias[cc + 1];
                    C[off]     = 0.5f * v0 * (1.f + erff(v0 * 0.70710678118654752f));
                    C[off + 1] = 0.5f * v1 * (1.f + erff(v1 * 0.70710678118654752f));
                } else if (EPI == 2) {
                    C[off]     += v0;
                    C[off + 1] += v1;
                } else {
                    C[off]     += v0 + bias[cc];
                    C[off + 1] += v1 + bias[cc + 1];
                }
            }
        }
    }
}

// ---------------- Fused local attention (rotary + flash softmax) ----------------
constexpr int KSTRIDE = 68;

__global__ __launch_bounds__(128)
void attn_kernel(const float* __restrict__ qkv, float* __restrict__ outp) {
    extern __shared__ float sm[];
    float* ks = sm;
    float* vs = sm + 256 * KSTRIDE;

    int w = blockIdx.x, head = blockIdx.y, b = blockIdx.z;
    int t = threadIdx.x;
    int qbase = w * WW;
    size_t rowbase = (size_t)b * N_;

    for (int idx = t; idx < 256 * 8; idx += 128) {
        int jj = idx >> 3;
        int d0 = (idx & 7) * 4;
        int p  = qbase - WW + jj;
        float4 lo = {0, 0, 0, 0}, hi = {0, 0, 0, 0};
        float4 olo = {0, 0, 0, 0}, ohi = {0, 0, 0, 0};
        if (p >= 0) {
            const float* kp = qkv + (rowbase + p) * QKVW + INNER + head * DH;
            lo = *(const float4*)(kp + d0);
            hi = *(const float4*)(kp + d0 + 32);
            #pragma unroll
            for (int u = 0; u < 4; ++u) {
                int d = d0 + u;
                float cs = g_cos[p * 32 + d];
                float sn = g_sin[p * 32 + d];
                float a  = (&lo.x)[u], b2 = (&hi.x)[u];
                (&olo.x)[u] = a * cs - b2 * sn;
                (&ohi.x)[u] = b2 * cs + a * sn;
            }
        }
        *(float4*)&ks[jj * KSTRIDE + d0]      = olo;
        *(float4*)&ks[jj * KSTRIDE + d0 + 32] = ohi;
    }
    for (int idx = t; idx < 256 * 16; idx += 128) {
        int jj = idx >> 4;
        int c4 = (idx & 15) * 4;
        int p  = qbase - WW + jj;
        float4 v4 = {0, 0, 0, 0};
        if (p >= 0)
            v4 = *(const float4*)(qkv + (rowbase + p) * QKVW + 2 * INNER + head * DH + c4);
        *(float4*)&vs[jj * KSTRIDE + c4] = v4;
    }

    int i = qbase + t;
    float q[64];
    {
        const float* qp = qkv + (rowbase + i) * QKVW + head * DH;
        #pragma unroll
        for (int d = 0; d < 32; ++d) {
            float cs = g_cos[i * 32 + d];
            float sn = g_sin[i * 32 + d];
            float a = qp[d], b2 = qp[d + 32];
            q[d]      = (a * cs - b2 * sn) * 0.125f;
            q[d + 32] = (b2 * cs + a * sn) * 0.125f;
        }
    }
    __syncthreads();

    float o[64];
    #pragma unroll
    for (int d = 0; d < 64; ++d) o[d] = 0.f;
    float m = -1e30f, l = 0.f;

    int rstart = (w == 0) ? (WW - t) : 0;
    for (int r = rstart; r <= WW; ++r) {
        int jj = t + r;
        const float* kr = &ks[jj * KSTRIDE];
        float s = 0.f;
        #pragma unroll
        for (int d4 = 0; d4 < 64; d4 += 4) {
            float4 k4 = *(const float4*)(kr + d4);
            s = fmaf(q[d4 + 0], k4.x, s);
            s = fmaf(q[d4 + 1], k4.y, s);
            s = fmaf(q[d4 + 2], k4.z, s);
            s = fmaf(q[d4 + 3], k4.w, s);
        }
        float mn   = fmaxf(m, s);
        float corr = __expf(m - mn);
        float pp   = __expf(s - mn);
        l = l * corr + pp;
        m = mn;
        const float* vr = &vs[jj * KSTRIDE];
        #pragma unroll
        for (int d4 = 0; d4 < 64; d4 += 4) {
            float4 v4 = *(const float4*)(vr + d4);
            o[d4 + 0] = fmaf(pp, v4.x, o[d4 + 0] * corr);
            o[d4 + 1] = fmaf(pp, v4.y, o[d4 + 1] * corr);
            o[d4 + 2] = fmaf(pp, v4.z, o[d4 + 2] * corr);
            o[d4 + 3] = fmaf(pp, v4.w, o[d4 + 3] * corr);
        }
    }

    float inv = 1.f / l;
    float* op = outp + (rowbase + i) * INNER + head * DH;
    #pragma unroll
    for (int d4 = 0; d4 < 64; d4 += 4) {
        float4 r4 = {o[d4] * inv, o[d4 + 1] * inv, o[d4 + 2] * inv, o[d4 + 3] * inv};
        *(float4*)(op + d4) = r4;
    }
}

// ---------------- Final LN + logits + slice ----------------
__global__ void final_kernel(const float* __restrict__ gg, const float* __restrict__ bb,
                             const float* __restrict__ wl, float* __restrict__ out) {
    int row = blockIdx.x, c = threadIdx.x;
    int n = row & (N_ - 1);
    if (n < SLACK || n >= N_ - SLACK) return;
    float v = g_h[(size_t)row * LD + c];
    __shared__ float sh[16];
    __shared__ float stat[2];
    float s = v, sq = v * v;
    #pragma unroll
    for (int o = 16; o > 0; o >>= 1) {
        s  += __shfl_down_sync(0xffffffffu, s, o);
        sq += __shfl_down_sync(0xffffffffu, sq, o);
    }
    if ((c & 31) == 0) { sh[c >> 5] = s; sh[8 + (c >> 5)] = sq; }
    __syncthreads();
    if (c == 0) {
        float S = 0.f, SQ = 0.f;
        #pragma unroll
        for (int i = 0; i < 8; i++) { S += sh[i]; SQ += sh[8 + i]; }
        float mean = S * (1.f / LD);
        stat[0] = mean;
        stat[1] = rsqrtf(SQ * (1.f / LD) - mean * mean + 1e-5f);
    }
    __syncthreads();
    float contrib = ((v - stat[0]) * stat[1] * gg[c] + bb[c]) * wl[c];
    #pragma unroll
    for (int o = 16; o > 0; o >>= 1)
        contrib += __shfl_down_sync(0xffffffffu, contrib, o);
    __syncthreads();
    if ((c & 31) == 0) sh[c >> 5] = contrib;
    __syncthreads();
    if (c == 0) {
        float T = 0.f;
        #pragma unroll
        for (int i = 0; i < 8; i++) T += sh[i];
        int bidx = row >> 12;
        out[bidx * (N_ - 2 * SLACK) + (n - SLACK)] = T;
    }
}

// ---------------- Launch ----------------
extern "C" void kernel_launch(void* const* d_in, const int* in_sizes, int n_in,
                              void* d_out, int out_size) {
    const float* x        = (const float*)d_in[0];
    const float* W_exp    = (const float*)d_in[1];
    const float* b_exp    = (const float*)d_in[2];
    const float* pos_emb  = (const float*)d_in[3];
    const float* ln_att_g = (const float*)d_in[4];
    const float* ln_att_b = (const float*)d_in[5];
    const float* Wqkv     = (const float*)d_in[6];
    const float* Wout     = (const float*)d_in[7];
    const float* ln_ff_g  = (const float*)d_in[8];
    const float* ln_ff_b  = (const float*)d_in[9];
    const float* W1       = (const float*)d_in[10];
    const float* b1       = (const float*)d_in[11];
    const float* W2       = (const float*)d_in[12];
    const float* b2       = (const float*)d_in[13];
    const float* ln_f_g   = (const float*)d_in[14];
    const float* ln_f_b   = (const float*)d_in[15];
    const float* W_logits = (const float*)d_in[16];
    float* out = (float*)d_out;

    float *ph, *py, *pqkv, *po, *pff;
    cudaGetSymbolAddress((void**)&ph,   g_h);
    cudaGetSymbolAddress((void**)&py,   g_y);
    cudaGetSymbolAddress((void**)&pqkv, g_qkv);
    cudaGetSymbolAddress((void**)&po,   g_o);
    cudaGetSymbolAddress((void**)&pff,  g_ff);

    int smem_attn = 2 * 256 * KSTRIDE * (int)sizeof(float);  // 139264 B
    cudaFuncSetAttribute(attn_kernel, cudaFuncAttributeMaxDynamicSharedMemorySize, smem_attn);

    rope_table_kernel<<<(N_ * 32 + 255) / 256, 256>>>();
    expand_kernel<<<R_, LD>>>(x, W_exp, b_exp, pos_emb);

    for (int l = 0; l < DEPTH; ++l) {
        ln_kernel<<<R_, LD>>>(ph, py, ln_att_g + l * LD, ln_att_b + l * LD);
        tgemm<0><<<dim3(QKVW / 128, R_ / 128), 256>>>(
            py, Wqkv + (size_t)l * LD * QKVW, pqkv, nullptr, R_, QKVW, LD);
        attn_kernel<<<dim3(N_ / WW, H_, B_), 128, smem_attn>>>(pqkv, po);
        tgemm<2><<<dim3(LD / 128, R_ / 128), 256>>>(
            po, Wout + (size_t)l * INNER * LD, ph, nullptr, R_, LD, INNER);
        ln_kernel<<<R_, LD>>>(ph, py, ln_ff_g + l * LD, ln_ff_b + l * LD);
        tgemm<1><<<dim3(FF / 128, R_ / 128), 256>>>(
            py, W1 + (size_t)l * LD * FF, pff, b1 + (size_t)l * FF, R_, FF, LD);
        tgemm<3><<<dim3(LD / 128, R_ / 128), 256>>>(
            pff, W2 + (size_t)l * FF * LD, ph, b2 + (size_t)l * LD, R_, LD, FF);
    }

    final_kernel<<<R_, LD>>>(ln_f_g, ln_f_b, W_logits, out);
}

// round 4
// speedup vs baseline: 2.1211x; 1.3939x over previous
#include <cuda_runtime.h>
#include <math.h>

// ---------------- Problem constants ----------------
constexpr int B_    = 16;
constexpr int N_    = 4096;
constexpr int LD    = 256;
constexpr int H_    = 8;
constexpr int DH    = 64;
constexpr int WW    = 128;
constexpr int INNER = 512;   // H_*DH
constexpr int DEPTH = 4;
constexpr int FF    = 1024;
constexpr int SLACK = 50;
constexpr int R_    = B_ * N_;          // 65536 rows
constexpr int QKVW  = 3 * INNER;        // 1536

// ---------------- Scratch ----------------
__device__ float g_h[(size_t)R_ * LD];
__device__ float g_y[(size_t)R_ * LD];
__device__ float g_qkv[(size_t)R_ * QKVW];
__device__ float g_o[(size_t)R_ * INNER];
__device__ float g_ff[(size_t)R_ * FF];
__device__ float g_cos[(size_t)N_ * 32];
__device__ float g_sin[(size_t)N_ * 32];
__device__ float g_wr[4194304];          // tf32-rounded weights
constexpr size_t WQKV_OFF = 0;
constexpr size_t WOUT_OFF = 1572864;
constexpr size_t W1_OFF   = 2097152;
constexpr size_t W2_OFF   = 3145728;

__device__ __forceinline__ unsigned f2tf(float x) {
    unsigned u;
    asm("cvt.rna.tf32.f32 %0, %1;" : "=r"(u) : "f"(x));
    return u;
}
__device__ __forceinline__ float f2tff(float x) { return __uint_as_float(f2tf(x)); }

__device__ __forceinline__ void mma_tf32(float* c, unsigned a0, unsigned a1,
                                         unsigned a2, unsigned a3,
                                         unsigned b0, unsigned b1) {
    asm volatile("mma.sync.aligned.m16n8k8.row.col.f32.tf32.tf32.f32 "
                 "{%0,%1,%2,%3}, {%4,%5,%6,%7}, {%8,%9}, {%0,%1,%2,%3};\n"
                 : "+f"(c[0]), "+f"(c[1]), "+f"(c[2]), "+f"(c[3])
                 : "r"(a0), "r"(a1), "r"(a2), "r"(a3), "r"(b0), "r"(b1));
}

__device__ __forceinline__ void cp16(void* smem, const void* g) {
    unsigned sa = (unsigned)__cvta_generic_to_shared(smem);
    asm volatile("cp.async.ca.shared.global [%0], [%1], 16;\n" :: "r"(sa), "l"(g));
}

// ---------------- RoPE table ----------------
__global__ void rope_table_kernel() {
    int idx = blockIdx.x * blockDim.x + threadIdx.x;
    if (idx >= N_ * 32) return;
    int n = idx >> 5, d = idx & 31;
    float invf = (float)(1.0 / pow(10000.0, (double)(2 * d) / 64.0));
    float angf = (float)n * invf;
    double a = (double)angf;
    g_cos[idx] = (float)cos(a);
    g_sin[idx] = (float)sin(a);
}

// ---------------- weight rounding ----------------
__global__ void round_tf32_kernel(const float* __restrict__ src, float* __restrict__ dst, int n) {
    int i = blockIdx.x * blockDim.x + threadIdx.x;
    if (i < n) dst[i] = f2tff(src[i]);
}

// ---------------- Expand ----------------
__global__ void expand_kernel(const float* __restrict__ x, const float* __restrict__ We,
                              const float* __restrict__ be, const float* __restrict__ pe) {
    int row = blockIdx.x;
    int c   = threadIdx.x;
    int n   = row & (N_ - 1);
    float x0 = x[row * 2 + 0], x1 = x[row * 2 + 1];
    g_h[(size_t)row * LD + c] = x0 * We[c] + x1 * We[LD + c] + be[c] + pe[n * LD + c];
}

// ---------------- LayerNorm (writes tf32-rounded output: GEMM A input) ----------------
__global__ void ln_kernel(const float* __restrict__ src, float* __restrict__ dst,
                          const float* __restrict__ gg, const float* __restrict__ bb) {
    int row = blockIdx.x, c = threadIdx.x;
    float v = src[(size_t)row * LD + c];
    float s = v, sq = v * v;
    #pragma unroll
    for (int o = 16; o > 0; o >>= 1) {
        s  += __shfl_down_sync(0xffffffffu, s, o);
        sq += __shfl_down_sync(0xffffffffu, sq, o);
    }
    __shared__ float sh[16];
    __shared__ float stat[2];
    if ((c & 31) == 0) { sh[c >> 5] = s; sh[8 + (c >> 5)] = sq; }
    __syncthreads();
    if (c == 0) {
        float S = 0.f, SQ = 0.f;
        #pragma unroll
        for (int i = 0; i < 8; i++) { S += sh[i]; SQ += sh[8 + i]; }
        float mean = S * (1.f / LD);
        stat[0] = mean;
        stat[1] = rsqrtf(SQ * (1.f / LD) - mean * mean + 1e-5f);
    }
    __syncthreads();
    dst[(size_t)row * LD + c] = f2tff((v - stat[0]) * stat[1] * gg[c] + bb[c]);
}

// ---------------- TF32 GEMM, double-buffered cp.async ----------------
constexpr int AS_STRIDE = 20;
constexpr int BS_STRIDE = 132;

template <int EPI>
__global__ __launch_bounds__(256, 2)
void tgemm(const float* __restrict__ A, const float* __restrict__ Bm,
           float* __restrict__ C, const float* __restrict__ bias,
           int M, int Nc, int K) {
    __shared__ float As[2][128][AS_STRIDE];
    __shared__ float Bs[2][16][BS_STRIDE];

    int tid  = threadIdx.x;
    int row0 = blockIdx.y * 128;
    int col0 = blockIdx.x * 128;
    int lane = tid & 31, w = tid >> 5;
    int gid  = lane >> 2, tig = lane & 3;
    int wr   = w & 1;
    int wc   = w >> 1;

    int ar = tid >> 2;
    int aj = tid & 3;
    int bk = tid >> 5;
    int bc = tid & 31;
    int s0 = ((bk & 3) << 2) | (bk >> 2);
    int s1 = s0 + 2;

    float acc[4][4][4];
    #pragma unroll
    for (int mi = 0; mi < 4; mi++)
        #pragma unroll
        for (int ni = 0; ni < 4; ni++)
            #pragma unroll
            for (int e = 0; e < 4; e++) acc[mi][ni][e] = 0.f;

    const float* Ap0 = A + (size_t)(row0 + ar) * K + aj * 4;
    const float* Ap1 = Ap0 + (size_t)64 * K;
    const float* Bp0 = Bm + (size_t)bk * Nc + col0 + bc * 4;
    const float* Bp1 = Bp0 + (size_t)8 * Nc;

    int NT = K >> 4;

    cp16(&Bs[0][s0][bc * 4], Bp0);
    cp16(&Bs[0][s1][bc * 4], Bp1);
    asm volatile("cp.async.commit_group;\n");
    {
        float4 a0 = *(const float4*)(Ap0);
        float4 a1 = *(const float4*)(Ap1);
        As[0][ar][aj]           = a0.x;  As[0][ar][aj + 4]       = a0.y;
        As[0][ar][aj + 8]       = a0.z;  As[0][ar][aj + 12]      = a0.w;
        As[0][ar + 64][aj]      = a1.x;  As[0][ar + 64][aj + 4]  = a1.y;
        As[0][ar + 64][aj + 8]  = a1.z;  As[0][ar + 64][aj + 12] = a1.w;
    }
    asm volatile("cp.async.wait_group 0;\n");
    __syncthreads();

    for (int it = 0; it < NT; it++) {
        int cur = it & 1, nxt = cur ^ 1;
        float4 aN0, aN1;
        if (it + 1 < NT) {
            const float* bsrc = Bp0 + (size_t)(it + 1) * 16 * Nc;
            cp16(&Bs[nxt][s0][bc * 4], bsrc);
            cp16(&Bs[nxt][s1][bc * 4], bsrc + (size_t)8 * Nc);
            asm volatile("cp.async.commit_group;\n");
            aN0 = *(const float4*)(Ap0 + (it + 1) * 16);
            aN1 = *(const float4*)(Ap1 + (it + 1) * 16);
        }

        {
            float4 fA[4][2];
            #pragma unroll
            for (int mi = 0; mi < 4; mi++) {
                int m = wr * 64 + mi * 16 + gid;
                fA[mi][0] = *(const float4*)&As[cur][m][tig * 4];
                fA[mi][1] = *(const float4*)&As[cur][m + 8][tig * 4];
            }
            #pragma unroll
            for (int ni = 0; ni < 4; ni++) {
                int n = wc * 32 + ni * 8 + gid;
                unsigned b00 = __float_as_uint(Bs[cur][tig * 4 + 0][n]);
                unsigned b01 = __float_as_uint(Bs[cur][tig * 4 + 1][n]);
                unsigned b10 = __float_as_uint(Bs[cur][tig * 4 + 2][n]);
                unsigned b11 = __float_as_uint(Bs[cur][tig * 4 + 3][n]);
                #pragma unroll
                for (int mi = 0; mi < 4; mi++) {
                    mma_tf32(acc[mi][ni],
                             __float_as_uint(fA[mi][0].x), __float_as_uint(fA[mi][1].x),
                             __float_as_uint(fA[mi][0].y), __float_as_uint(fA[mi][1].y),
                             b00, b01);
                    mma_tf32(acc[mi][ni],
                             __float_as_uint(fA[mi][0].z), __float_as_uint(fA[mi][1].z),
                             __float_as_uint(fA[mi][0].w), __float_as_uint(fA[mi][1].w),
                             b10, b11);
                }
            }
        }

        if (it + 1 < NT) {
            As[nxt][ar][aj]           = aN0.x;  As[nxt][ar][aj + 4]       = aN0.y;
            As[nxt][ar][aj + 8]       = aN0.z;  As[nxt][ar][aj + 12]      = aN0.w;
            As[nxt][ar + 64][aj]      = aN1.x;  As[nxt][ar + 64][aj + 4]  = aN1.y;
            As[nxt][ar + 64][aj + 8]  = aN1.z;  As[nxt][ar + 64][aj + 12] = aN1.w;
            asm volatile("cp.async.wait_group 0;\n");
            __syncthreads();
        }
    }

    #pragma unroll
    for (int mi = 0; mi < 4; mi++) {
        int ra = row0 + wr * 64 + mi * 16 + gid;
        #pragma unroll
        for (int ni = 0; ni < 4; ni++) {
            int cc = col0 + wc * 32 + ni * 8 + tig * 2;
            #pragma unroll
            for (int half = 0; half < 2; half++) {
                int r = ra + half * 8;
                float v0 = acc[mi][ni][half * 2 + 0];
                float v1 = acc[mi][ni][half * 2 + 1];
                size_t off = (size_t)r * Nc + cc;
                if (EPI == 0) {
                    C[off]     = v0;
                    C[off + 1] = v1;
                } else if (EPI == 1) {
                    v0 += bias[cc];
                    v1 += bias[cc + 1];
                    C[off]     = f2tff(0.5f * v0 * (1.f + erff(v0 * 0.70710678118654752f)));
                    C[off + 1] = f2tff(0.5f * v1 * (1.f + erff(v1 * 0.70710678118654752f)));
                } else if (EPI == 2) {
                    C[off]     += v0;
                    C[off + 1] += v1;
                } else {
                    C[off]     += v0 + bias[cc];
                    C[off + 1] += v1 + bias[cc + 1];
                }
            }
        }
    }
}

// ---------------- Tensor-core flash local attention ----------------
constexpr int KS2_ST = 80;
constexpr int VS2_ST = 272;
constexpr int QP_ST  = 80;
constexpr int ATTN_SMEM = (256 * KS2_ST + 64 * VS2_ST + 128 * QP_ST) * 4;

__global__ __launch_bounds__(256)
void attn_mma_kernel(const float* __restrict__ qkv, float* __restrict__ outp) {
    extern __shared__ float sm[];
    float* Ks2 = sm;
    float* Vs2 = sm + 256 * KS2_ST;
    float* QPs = Vs2 + 64 * VS2_ST;

    int w = blockIdx.x, head = blockIdx.y, b = blockIdx.z;
    int tid  = threadIdx.x;
    int lane = tid & 31;
    int wm   = tid >> 5;
    int gid  = lane >> 2, tig = lane & 3;
    int qbase = w * WW;
    size_t rowbase = (size_t)b * N_;

    {
        int jj = tid;
        int p = qbase - WW + jj;
        float kv[64];
        if (p >= 0) {
            const float* kp = qkv + (rowbase + p) * QKVW + INNER + head * DH;
            float raw[64];
            #pragma unroll
            for (int d4 = 0; d4 < 64; d4 += 4)
                *(float4*)&raw[d4] = *(const float4*)(kp + d4);
            #pragma unroll
            for (int d = 0; d < 32; d++) {
                float cs = g_cos[p * 32 + d], sn = g_sin[p * 32 + d];
                kv[d]      = f2tff(raw[d] * cs - raw[d + 32] * sn);
                kv[d + 32] = f2tff(raw[d + 32] * cs + raw[d] * sn);
            }
        } else {
            #pragma unroll
            for (int d = 0; d < 64; d++) kv[d] = 0.f;
        }
        #pragma unroll
        for (int bb = 0; bb < 4; bb++)
            #pragma unroll
            for (int tg = 0; tg < 4; tg++) {
                float4 f = {kv[bb*16+tg], kv[bb*16+tg+4], kv[bb*16+tg+8], kv[bb*16+tg+12]};
                *(float4*)&Ks2[jj * KS2_ST + bb * 16 + tg * 4] = f;
            }
    }
    {
        int jj = tid;
        int p = qbase - WW + jj;
        int wj = jj & 15;
        int colp = (jj >> 4) * 16 + (wj & 3) * 4 + (wj >> 2);
        if (p >= 0) {
            const float* vp = qkv + (rowbase + p) * QKVW + 2 * INNER + head * DH;
            #pragma unroll
            for (int d4 = 0; d4 < 64; d4 += 4) {
                float4 v4 = *(const float4*)(vp + d4);
                Vs2[(d4+0) * VS2_ST + colp] = f2tff(v4.x);
                Vs2[(d4+1) * VS2_ST + colp] = f2tff(v4.y);
                Vs2[(d4+2) * VS2_ST + colp] = f2tff(v4.z);
                Vs2[(d4+3) * VS2_ST + colp] = f2tff(v4.w);
            }
        } else {
            #pragma unroll
            for (int d = 0; d < 64; d++) Vs2[d * VS2_ST + colp] = 0.f;
        }
    }
    if (tid < 128) {
        int r = tid;
        int i = qbase + r;
        const float* qp = qkv + (rowbase + i) * QKVW + head * DH;
        float raw[64], qv[64];
        #pragma unroll
        for (int d4 = 0; d4 < 64; d4 += 4)
            *(float4*)&raw[d4] = *(const float4*)(qp + d4);
        #pragma unroll
        for (int d = 0; d < 32; d++) {
            float cs = g_cos[i * 32 + d], sn = g_sin[i * 32 + d];
            qv[d]      = f2tff((raw[d] * cs - raw[d + 32] * sn) * 0.125f);
            qv[d + 32] = f2tff((raw[d + 32] * cs + raw[d] * sn) * 0.125f);
        }
        #pragma unroll
        for (int bb = 0; bb < 4; bb++)
            #pragma unroll
            for (int tg = 0; tg < 4; tg++) {
                float4 f = {qv[bb*16+tg], qv[bb*16+tg+4], qv[bb*16+tg+8], qv[bb*16+tg+12]};
                *(float4*)&QPs[r * QP_ST + bb * 16 + tg * 4] = f;
            }
    }
    __syncthreads();

    unsigned qa[8][4];
    {
        int rA = wm * 16 + gid, rB = rA + 8;
        #pragma unroll
        for (int bb = 0; bb < 4; bb++) {
            float4 lo = *(const float4*)&QPs[rA * QP_ST + bb * 16 + tig * 4];
            float4 hi = *(const float4*)&QPs[rB * QP_ST + bb * 16 + tig * 4];
            qa[2*bb][0]   = __float_as_uint(lo.x); qa[2*bb][1]   = __float_as_uint(hi.x);
            qa[2*bb][2]   = __float_as_uint(lo.y); qa[2*bb][3]   = __float_as_uint(hi.y);
            qa[2*bb+1][0] = __float_as_uint(lo.z); qa[2*bb+1][1] = __float_as_uint(hi.z);
            qa[2*bb+1][2] = __float_as_uint(lo.w); qa[2*bb+1][3] = __float_as_uint(hi.w);
        }
    }

    float O[8][4];
    #pragma unroll
    for (int nf = 0; nf < 8; nf++)
        #pragma unroll
        for (int e = 0; e < 4; e++) O[nf][e] = 0.f;
    float m0 = -1e30f, m1 = -1e30f, l0 = 0.f, l1 = 0.f;

    float* Ps = QPs + (size_t)(wm * 16) * QP_ST;
    int i0 = qbase + wm * 16 + gid;
    int i1 = i0 + 8;

    int clo = wm >> 2, chi = clo + 2;
    if (w == 0) clo = 2;

    for (int c = clo; c <= chi; c++) {
        float S[8][4];
        #pragma unroll
        for (int nf = 0; nf < 8; nf++)
            #pragma unroll
            for (int e = 0; e < 4; e++) S[nf][e] = 0.f;
        #pragma unroll
        for (int nf = 0; nf < 8; nf++) {
            int n = c * 64 + nf * 8 + gid;
            #pragma unroll
            for (int bb = 0; bb < 4; bb++) {
                float4 f = *(const float4*)&Ks2[n * KS2_ST + bb * 16 + tig * 4];
                mma_tf32(S[nf], qa[2*bb][0], qa[2*bb][1], qa[2*bb][2], qa[2*bb][3],
                         __float_as_uint(f.x), __float_as_uint(f.y));
                mma_tf32(S[nf], qa[2*bb+1][0], qa[2*bb+1][1], qa[2*bb+1][2], qa[2*bb+1][3],
                         __float_as_uint(f.z), __float_as_uint(f.w));
            }
        }
        int jbase = qbase - WW + c * 64;
        float rmax0 = -1e30f, rmax1 = -1e30f;
        #pragma unroll
        for (int nf = 0; nf < 8; nf++) {
            int j0 = jbase + nf * 8 + 2 * tig;
            if (i0 < j0     || i0 - j0 > WW)     S[nf][0] = -1e9f;
            if (i0 < j0 + 1 || i0 - j0 - 1 > WW) S[nf][1] = -1e9f;
            if (i1 < j0     || i1 - j0 > WW)     S[nf][2] = -1e9f;
            if (i1 < j0 + 1 || i1 - j0 - 1 > WW) S[nf][3] = -1e9f;
            rmax0 = fmaxf(rmax0, fmaxf(S[nf][0], S[nf][1]));
            rmax1 = fmaxf(rmax1, fmaxf(S[nf][2], S[nf][3]));
        }
        rmax0 = fmaxf(rmax0, __shfl_xor_sync(0xffffffffu, rmax0, 1));
        rmax0 = fmaxf(rmax0, __shfl_xor_sync(0xffffffffu, rmax0, 2));
        rmax1 = fmaxf(rmax1, __shfl_xor_sync(0xffffffffu, rmax1, 1));
        rmax1 = fmaxf(rmax1, __shfl_xor_sync(0xffffffffu, rmax1, 2));
        float mn0 = fmaxf(m0, rmax0), mn1 = fmaxf(m1, rmax1);
        float cor0 = __expf(m0 - mn0), cor1 = __expf(m1 - mn1);
        m0 = mn0; m1 = mn1;
        float ls0 = 0.f, ls1 = 0.f;
        #pragma unroll
        for (int nf = 0; nf < 8; nf++) {
            float p0 = __expf(S[nf][0] - mn0);
            float p1 = __expf(S[nf][1] - mn0);
            float p2 = __expf(S[nf][2] - mn1);
            float p3 = __expf(S[nf][3] - mn1);
            ls0 += p0 + p1;
            ls1 += p2 + p3;
            int n0 = nf * 8 + 2 * tig;
            int n1 = n0 + 1;
            int cp0 = (n0 >> 4) * 16 + ((n0 & 15) & 3) * 4 + ((n0 & 15) >> 2);
            int cp1 = (n1 >> 4) * 16 + ((n1 & 15) & 3) * 4 + ((n1 & 15) >> 2);
            Ps[gid * QP_ST + cp0]       = f2tff(p0);
            Ps[gid * QP_ST + cp1]       = f2tff(p1);
            Ps[(gid + 8) * QP_ST + cp0] = f2tff(p2);
            Ps[(gid + 8) * QP_ST + cp1] = f2tff(p3);
        }
        l0 = l0 * cor0 + ls0;
        l1 = l1 * cor1 + ls1;
        #pragma unroll
        for (int nf = 0; nf < 8; nf++) {
            O[nf][0] *= cor0; O[nf][1] *= cor0;
            O[nf][2] *= cor1; O[nf][3] *= cor1;
        }
        __syncwarp();
        unsigned pa[8][4];
        #pragma unroll
        for (int bb = 0; bb < 4; bb++) {
            float4 lo = *(const float4*)&Ps[gid * QP_ST + bb * 16 + tig * 4];
            float4 hi = *(const float4*)&Ps[(gid + 8) * QP_ST + bb * 16 + tig * 4];
            pa[2*bb][0]   = __float_as_uint(lo.x); pa[2*bb][1]   = __float_as_uint(hi.x);
            pa[2*bb][2]   = __float_as_uint(lo.y); pa[2*bb][3]   = __float_as_uint(hi.y);
            pa[2*bb+1][0] = __float_as_uint(lo.z); pa[2*bb+1][1] = __float_as_uint(hi.z);
            pa[2*bb+1][2] = __float_as_uint(lo.w); pa[2*bb+1][3] = __float_as_uint(hi.w);
        }
        #pragma unroll
        for (int nd = 0; nd < 8; nd++) {
            int n = nd * 8 + gid;
            #pragma unroll
            for (int bb = 0; bb < 4; bb++) {
                float4 f = *(const float4*)&Vs2[n * VS2_ST + c * 64 + bb * 16 + tig * 4];
                mma_tf32(O[nd], pa[2*bb][0], pa[2*bb][1], pa[2*bb][2], pa[2*bb][3],
                         __float_as_uint(f.x), __float_as_uint(f.y));
                mma_tf32(O[nd], pa[2*bb+1][0], pa[2*bb+1][1], pa[2*bb+1][2], pa[2*bb+1][3],
                         __float_as_uint(f.z), __float_as_uint(f.w));
            }
        }
        __syncwarp();
    }

    l0 += __shfl_xor_sync(0xffffffffu, l0, 1);
    l0 += __shfl_xor_sync(0xffffffffu, l0, 2);
    l1 += __shfl_xor_sync(0xffffffffu, l1, 1);
    l1 += __shfl_xor_sync(0xffffffffu, l1, 2);
    float inv0 = 1.f / l0, inv1 = 1.f / l1;

    float* op0 = outp + (rowbase + i0) * INNER + head * DH;
    float* op1 = outp + (rowbase + i1) * INNER + head * DH;
    #pragma unroll
    for (int nd = 0; nd < 8; nd++) {
        int d0 = nd * 8 + 2 * tig;
        op0[d0]     = f2tff(O[nd][0] * inv0);
        op0[d0 + 1] = f2tff(O[nd][1] * inv0);
        op1[d0]     = f2tff(O[nd][2] * inv1);
        op1[d0 + 1] = f2tff(O[nd][3] * inv1);
    }
}

// ---------------- Final LN + logits + slice ----------------
__global__ void final_kernel(const float* __restrict__ gg, const float* __restrict__ bb,
                             const float* __restrict__ wl, float* __restrict__ out) {
    int row = blockIdx.x, c = threadIdx.x;
    int n = row & (N_ - 1);
    if (n < SLACK || n >= N_ - SLACK) return;
    float v = g_h[(size_t)row * LD + c];
    __shared__ float sh[16];
    __shared__ float stat[2];
    float s = v, sq = v * v;
    #pragma unroll
    for (int o = 16; o > 0; o >>= 1) {
        s  += __shfl_down_sync(0xffffffffu, s, o);
        sq += __shfl_down_sync(0xffffffffu, sq, o);
    }
    if ((c & 31) == 0) { sh[c >> 5] = s; sh[8 + (c >> 5)] = sq; }
    __syncthreads();
    if (c == 0) {
        float S = 0.f, SQ = 0.f;
        #pragma unroll
        for (int i = 0; i < 8; i++) { S += sh[i]; SQ += sh[8 + i]; }
        float mean = S * (1.f / LD);
        stat[0] = mean;
        stat[1] = rsqrtf(SQ * (1.f / LD) - mean * mean + 1e-5f);
    }
    __syncthreads();
    float contrib = ((v - stat[0]) * stat[1] * gg[c] + bb[c]) * wl[c];
    #pragma unroll
    for (int o = 16; o > 0; o >>= 1)
        contrib += __shfl_down_sync(0xffffffffu, contrib, o);
    __syncthreads();
    if ((c & 31) == 0) sh[c >> 5] = contrib;
    __syncthreads();
    if (c == 0) {
        float T = 0.f;
        #pragma unroll
        for (int i = 0; i < 8; i++) T += sh[i];
        int bidx = row >> 12;
        out[bidx * (N_ - 2 * SLACK) + (n - SLACK)] = T;
    }
}

// ---------------- Launch ----------------
extern "C" void kernel_launch(void* const* d_in, const int* in_sizes, int n_in,
                              void* d_out, int out_size) {
    const float* x        = (const float*)d_in[0];
    const float* W_exp    = (const float*)d_in[1];
    const float* b_exp    = (const float*)d_in[2];
    const float* pos_emb  = (const float*)d_in[3];
    const float* ln_att_g = (const float*)d_in[4];
    const float* ln_att_b = (const float*)d_in[5];
    const float* Wqkv     = (const float*)d_in[6];
    const float* Wout     = (const float*)d_in[7];
    const float* ln_ff_g  = (const float*)d_in[8];
    const float* ln_ff_b  = (const float*)d_in[9];
    const float* W1       = (const float*)d_in[10];
    const float* b1       = (const float*)d_in[11];
    const float* W2       = (const float*)d_in[12];
    const float* b2       = (const float*)d_in[13];
    const float* ln_f_g   = (const float*)d_in[14];
    const float* ln_f_b   = (const float*)d_in[15];
    const float* W_logits = (const float*)d_in[16];
    float* out = (float*)d_out;

    float *ph, *py, *pqkv, *po, *pff, *pwr;
    cudaGetSymbolAddress((void**)&ph,   g_h);
    cudaGetSymbolAddress((void**)&py,   g_y);
    cudaGetSymbolAddress((void**)&pqkv, g_qkv);
    cudaGetSymbolAddress((void**)&po,   g_o);
    cudaGetSymbolAddress((void**)&pff,  g_ff);
    cudaGetSymbolAddress((void**)&pwr,  g_wr);

    cudaFuncSetAttribute(attn_mma_kernel, cudaFuncAttributeMaxDynamicSharedMemorySize, ATTN_SMEM);

    rope_table_kernel<<<(N_ * 32 + 255) / 256, 256>>>();
    round_tf32_kernel<<<(DEPTH*LD*QKVW + 255)/256, 256>>>(Wqkv, pwr + WQKV_OFF, DEPTH*LD*QKVW);
    round_tf32_kernel<<<(DEPTH*INNER*LD + 255)/256, 256>>>(Wout, pwr + WOUT_OFF, DEPTH*INNER*LD);
    round_tf32_kernel<<<(DEPTH*LD*FF + 255)/256, 256>>>(W1, pwr + W1_OFF, DEPTH*LD*FF);
    round_tf32_kernel<<<(DEPTH*FF*LD + 255)/256, 256>>>(W2, pwr + W2_OFF, DEPTH*FF*LD);
    expand_kernel<<<R_, LD>>>(x, W_exp, b_exp, pos_emb);

    for (int l = 0; l < DEPTH; ++l) {
        ln_kernel<<<R_, LD>>>(ph, py, ln_att_g + l * LD, ln_att_b + l * LD);
        tgemm<0><<<dim3(QKVW / 128, R_ / 128), 256>>>(
            py, pwr + WQKV_OFF + (size_t)l * LD * QKVW, pqkv, nullptr, R_, QKVW, LD);
        attn_mma_kernel<<<dim3(N_ / WW, H_, B_), 256, ATTN_SMEM>>>(pqkv, po);
        tgemm<2><<<dim3(LD / 128, R_ / 128), 256>>>(
            po, pwr + WOUT_OFF + (size_t)l * INNER * LD, ph, nullptr, R_, LD, INNER);
        ln_kernel<<<R_, LD>>>(ph, py, ln_ff_g + l * LD, ln_ff_b + l * LD);
        tgemm<1><<<dim3(FF / 128, R_ / 128), 256>>>(
            py, pwr + W1_OFF + (size_t)l * LD * FF, pff, b1 + (size_t)l * FF, R_, FF, LD);
        tgemm<3><<<dim3(LD / 128, R_ / 128), 256>>>(
            pff, pwr + W2_OFF + (size_t)l * FF * LD, ph, b2 + (size_t)l * LD, R_, LD, FF);
    }

    final_kernel<<<R_, LD>>>(ln_f_g, ln_f_b, W_logits, out);
}

// round 5
// speedup vs baseline: 2.1776x; 1.0267x over previous
#include <cuda_runtime.h>
#include <math.h>

// ---------------- Problem constants ----------------
constexpr int B_    = 16;
constexpr int N_    = 4096;
constexpr int LD    = 256;
constexpr int H_    = 8;
constexpr int DH    = 64;
constexpr int WW    = 128;
constexpr int INNER = 512;   // H_*DH
constexpr int DEPTH = 4;
constexpr int FF    = 1024;
constexpr int SLACK = 50;
constexpr int R_    = B_ * N_;          // 65536 rows
constexpr int QKVW  = 3 * INNER;        // 1536

// ---------------- Scratch ----------------
__device__ float g_h[(size_t)R_ * LD];
__device__ float g_y[(size_t)R_ * LD];
__device__ float g_qkv[(size_t)R_ * QKVW];
__device__ float g_o[(size_t)R_ * INNER];
__device__ float g_ff[(size_t)R_ * FF];
__device__ float g_cos[(size_t)N_ * 32];
__device__ float g_sin[(size_t)N_ * 32];
__device__ float g_wr[4194304];          // tf32-rounded weights
constexpr size_t WQKV_OFF = 0;
constexpr size_t WOUT_OFF = 1572864;
constexpr size_t W1_OFF   = 2097152;
constexpr size_t W2_OFF   = 3145728;

__device__ __forceinline__ unsigned f2tf(float x) {
    unsigned u;
    asm("cvt.rna.tf32.f32 %0, %1;" : "=r"(u) : "f"(x));
    return u;
}
__device__ __forceinline__ float f2tff(float x) { return __uint_as_float(f2tf(x)); }

__device__ __forceinline__ void mma_tf32(float* c, unsigned a0, unsigned a1,
                                         unsigned a2, unsigned a3,
                                         unsigned b0, unsigned b1) {
    asm volatile("mma.sync.aligned.m16n8k8.row.col.f32.tf32.tf32.f32 "
                 "{%0,%1,%2,%3}, {%4,%5,%6,%7}, {%8,%9}, {%0,%1,%2,%3};\n"
                 : "+f"(c[0]), "+f"(c[1]), "+f"(c[2]), "+f"(c[3])
                 : "r"(a0), "r"(a1), "r"(a2), "r"(a3), "r"(b0), "r"(b1));
}

__device__ __forceinline__ void cp16(void* smem, const void* g) {
    unsigned sa = (unsigned)__cvta_generic_to_shared(smem);
    asm volatile("cp.async.ca.shared.global [%0], [%1], 16;\n" :: "r"(sa), "l"(g));
}

// ---------------- RoPE table ----------------
__global__ void rope_table_kernel() {
    int idx = blockIdx.x * blockDim.x + threadIdx.x;
    if (idx >= N_ * 32) return;
    int n = idx >> 5, d = idx & 31;
    float invf = (float)(1.0 / pow(10000.0, (double)(2 * d) / 64.0));
    float angf = (float)n * invf;
    double a = (double)angf;
    g_cos[idx] = (float)cos(a);
    g_sin[idx] = (float)sin(a);
}

// ---------------- weight rounding ----------------
__global__ void round_tf32_kernel(const float* __restrict__ src, float* __restrict__ dst, int n) {
    int i = blockIdx.x * blockDim.x + threadIdx.x;
    if (i < n) dst[i] = f2tff(src[i]);
}

// ---------------- Expand ----------------
__global__ void expand_kernel(const float* __restrict__ x, const float* __restrict__ We,
                              const float* __restrict__ be, const float* __restrict__ pe) {
    int row = blockIdx.x;
    int c   = threadIdx.x;
    int n   = row & (N_ - 1);
    float x0 = x[row * 2 + 0], x1 = x[row * 2 + 1];
    g_h[(size_t)row * LD + c] = x0 * We[c] + x1 * We[LD + c] + be[c] + pe[n * LD + c];
}

// ---------------- LayerNorm (writes tf32-rounded output) ----------------
__global__ void ln_kernel(const float* __restrict__ src, float* __restrict__ dst,
                          const float* __restrict__ gg, const float* __restrict__ bb) {
    int row = blockIdx.x, c = threadIdx.x;
    float v = src[(size_t)row * LD + c];
    float s = v, sq = v * v;
    #pragma unroll
    for (int o = 16; o > 0; o >>= 1) {
        s  += __shfl_down_sync(0xffffffffu, s, o);
        sq += __shfl_down_sync(0xffffffffu, sq, o);
    }
    __shared__ float sh[16];
    __shared__ float stat[2];
    if ((c & 31) == 0) { sh[c >> 5] = s; sh[8 + (c >> 5)] = sq; }
    __syncthreads();
    if (c == 0) {
        float S = 0.f, SQ = 0.f;
        #pragma unroll
        for (int i = 0; i < 8; i++) { S += sh[i]; SQ += sh[8 + i]; }
        float mean = S * (1.f / LD);
        stat[0] = mean;
        stat[1] = rsqrtf(SQ * (1.f / LD) - mean * mean + 1e-5f);
    }
    __syncthreads();
    dst[(size_t)row * LD + c] = f2tff((v - stat[0]) * stat[1] * gg[c] + bb[c]);
}

// ---------------- TF32 GEMM: plain k-major smem, all-cp.async, 3 stages ----------------
constexpr int AS_STRIDE = 20;   // 16 + 4 pad
constexpr int BS_STRIDE = 132;  // 128 + 4 pad
constexpr int TG_STAGES = 3;
constexpr int AS_FLOATS = 128 * AS_STRIDE;            // per stage
constexpr int BS_FLOATS = 16 * BS_STRIDE;             // per stage
constexpr int TG_SMEM = (TG_STAGES * AS_FLOATS + TG_STAGES * BS_FLOATS) * 4;  // 56064 B

template <int EPI>
__global__ __launch_bounds__(256, 2)
void tgemm(const float* __restrict__ A, const float* __restrict__ Bm,
           float* __restrict__ C, const float* __restrict__ bias,
           int M, int Nc, int K) {
    extern __shared__ float smp[];
    float* AsBase = smp;                                   // [stage][128][AS_STRIDE]
    float* BsBase = smp + TG_STAGES * AS_FLOATS;           // [stage][16][BS_STRIDE]

    int tid  = threadIdx.x;
    int row0 = blockIdx.y * 128;
    int col0 = blockIdx.x * 128;
    int lane = tid & 31, w = tid >> 5;
    int gid  = lane >> 2, tig = lane & 3;
    int wr   = w & 1;
    int wc   = w >> 1;

    // staging indices
    int ar = tid >> 2;        // 0..63, plus +64 second half
    int aq = tid & 3;         // k-quad within 16
    int bk = tid >> 5;        // 0..7, plus +8
    int bc = tid & 31;        // n-quad

    const float* ApS = A + (size_t)(row0 + ar) * K + aq * 4;
    const float* BpS = Bm + (size_t)bk * Nc + col0 + bc * 4;

    float acc[4][4][4];
    #pragma unroll
    for (int mi = 0; mi < 4; mi++)
        #pragma unroll
        for (int ni = 0; ni < 4; ni++)
            #pragma unroll
            for (int e = 0; e < 4; e++) acc[mi][ni][e] = 0.f;

    int NT = K >> 4;

    // stage issuer: tile index kti into buffer buf
    auto stage = [&](int kti, int buf) {
        float* Asb = AsBase + buf * AS_FLOATS;
        float* Bsb = BsBase + buf * BS_FLOATS;
        const float* as = ApS + kti * 16;
        cp16(&Asb[ar * AS_STRIDE + aq * 4], as);
        cp16(&Asb[(ar + 64) * AS_STRIDE + aq * 4], as + (size_t)64 * K);
        const float* bs = BpS + (size_t)kti * 16 * Nc;
        cp16(&Bsb[bk * BS_STRIDE + bc * 4], bs);
        cp16(&Bsb[(bk + 8) * BS_STRIDE + bc * 4], bs + (size_t)8 * Nc);
    };

    // prologue: stages 0 and 1 (NT >= 16 always here)
    stage(0, 0);
    asm volatile("cp.async.commit_group;\n");
    stage(1, 1);
    asm volatile("cp.async.commit_group;\n");

    for (int it = 0; it < NT; it++) {
        int cur = it % TG_STAGES;
        asm volatile("cp.async.wait_group 1;\n");
        __syncthreads();

        // issue stage it+2 into buffer (it+2)%3 (== buffer of it-1, freed by the barrier)
        if (it + 2 < NT) stage(it + 2, (it + 2) % TG_STAGES);
        asm volatile("cp.async.commit_group;\n");

        const float* Asb = AsBase + cur * AS_FLOATS;
        const float* Bsb = BsBase + cur * BS_FLOATS;

        float4 fA[4][2];
        #pragma unroll
        for (int mi = 0; mi < 4; mi++) {
            int m = wr * 64 + mi * 16 + gid;
            fA[mi][0] = *(const float4*)&Asb[m * AS_STRIDE + tig * 4];
            fA[mi][1] = *(const float4*)&Asb[(m + 8) * AS_STRIDE + tig * 4];
        }
        #pragma unroll
        for (int ni = 0; ni < 4; ni++) {
            int n = wc * 32 + ni * 8 + gid;
            unsigned b00 = __float_as_uint(Bsb[(tig * 4 + 0) * BS_STRIDE + n]);
            unsigned b01 = __float_as_uint(Bsb[(tig * 4 + 1) * BS_STRIDE + n]);
            unsigned b10 = __float_as_uint(Bsb[(tig * 4 + 2) * BS_STRIDE + n]);
            unsigned b11 = __float_as_uint(Bsb[(tig * 4 + 3) * BS_STRIDE + n]);
            #pragma unroll
            for (int mi = 0; mi < 4; mi++) {
                mma_tf32(acc[mi][ni],
                         __float_as_uint(fA[mi][0].x), __float_as_uint(fA[mi][1].x),
                         __float_as_uint(fA[mi][0].y), __float_as_uint(fA[mi][1].y),
                         b00, b01);
                mma_tf32(acc[mi][ni],
                         __float_as_uint(fA[mi][0].z), __float_as_uint(fA[mi][1].z),
                         __float_as_uint(fA[mi][0].w), __float_as_uint(fA[mi][1].w),
                         b10, b11);
            }
        }
    }

    #pragma unroll
    for (int mi = 0; mi < 4; mi++) {
        int ra = row0 + wr * 64 + mi * 16 + gid;
        #pragma unroll
        for (int ni = 0; ni < 4; ni++) {
            int cc = col0 + wc * 32 + ni * 8 + tig * 2;
            #pragma unroll
            for (int half = 0; half < 2; half++) {
                int r = ra + half * 8;
                float v0 = acc[mi][ni][half * 2 + 0];
                float v1 = acc[mi][ni][half * 2 + 1];
                size_t off = (size_t)r * Nc + cc;
                if (EPI == 0) {
                    C[off]     = v0;
                    C[off + 1] = v1;
                } else if (EPI == 1) {
                    v0 += bias[cc];
                    v1 += bias[cc + 1];
                    C[off]     = f2tff(0.5f * v0 * (1.f + erff(v0 * 0.70710678118654752f)));
                    C[off + 1] = f2tff(0.5f * v1 * (1.f + erff(v1 * 0.70710678118654752f)));
                } else if (EPI == 2) {
                    C[off]     += v0;
                    C[off + 1] += v1;
                } else {
                    C[off]     += v0 + bias[cc];
                    C[off + 1] += v1 + bias[cc + 1];
                }
            }
        }
    }
}

// ---------------- Tensor-core flash local attention ----------------
constexpr int KS2_ST = 80;
constexpr int VS2_ST = 272;
constexpr int QP_ST  = 80;
constexpr int ATTN_SMEM = (256 * KS2_ST + 64 * VS2_ST + 128 * QP_ST) * 4;

__global__ __launch_bounds__(256)
void attn_mma_kernel(const float* __restrict__ qkv, float* __restrict__ outp) {
    extern __shared__ float sm[];
    float* Ks2 = sm;
    float* Vs2 = sm + 256 * KS2_ST;
    float* QPs = Vs2 + 64 * VS2_ST;

    int w = blockIdx.x, head = blockIdx.y, b = blockIdx.z;
    int tid  = threadIdx.x;
    int lane = tid & 31;
    int wm   = tid >> 5;
    int gid  = lane >> 2, tig = lane & 3;
    int qbase = w * WW;
    size_t rowbase = (size_t)b * N_;

    {
        int jj = tid;
        int p = qbase - WW + jj;
        float kv[64];
        if (p >= 0) {
            const float* kp = qkv + (rowbase + p) * QKVW + INNER + head * DH;
            float raw[64];
            #pragma unroll
            for (int d4 = 0; d4 < 64; d4 += 4)
                *(float4*)&raw[d4] = *(const float4*)(kp + d4);
            #pragma unroll
            for (int d = 0; d < 32; d++) {
                float cs = g_cos[p * 32 + d], sn = g_sin[p * 32 + d];
                kv[d]      = f2tff(raw[d] * cs - raw[d + 32] * sn);
                kv[d + 32] = f2tff(raw[d + 32] * cs + raw[d] * sn);
            }
        } else {
            #pragma unroll
            for (int d = 0; d < 64; d++) kv[d] = 0.f;
        }
        #pragma unroll
        for (int bb = 0; bb < 4; bb++)
            #pragma unroll
            for (int tg = 0; tg < 4; tg++) {
                float4 f = {kv[bb*16+tg], kv[bb*16+tg+4], kv[bb*16+tg+8], kv[bb*16+tg+12]};
                *(float4*)&Ks2[jj * KS2_ST + bb * 16 + tg * 4] = f;
            }
    }
    {
        int jj = tid;
        int p = qbase - WW + jj;
        int wj = jj & 15;
        int colp = (jj >> 4) * 16 + (wj & 3) * 4 + (wj >> 2);
        if (p >= 0) {
            const float* vp = qkv + (rowbase + p) * QKVW + 2 * INNER + head * DH;
            #pragma unroll
            for (int d4 = 0; d4 < 64; d4 += 4) {
                float4 v4 = *(const float4*)(vp + d4);
                Vs2[(d4+0) * VS2_ST + colp] = f2tff(v4.x);
                Vs2[(d4+1) * VS2_ST + colp] = f2tff(v4.y);
                Vs2[(d4+2) * VS2_ST + colp] = f2tff(v4.z);
                Vs2[(d4+3) * VS2_ST + colp] = f2tff(v4.w);
            }
        } else {
            #pragma unroll
            for (int d = 0; d < 64; d++) Vs2[d * VS2_ST + colp] = 0.f;
        }
    }
    if (tid < 128) {
        int r = tid;
        int i = qbase + r;
        const float* qp = qkv + (rowbase + i) * QKVW + head * DH;
        float raw[64], qv[64];
        #pragma unroll
        for (int d4 = 0; d4 < 64; d4 += 4)
            *(float4*)&raw[d4] = *(const float4*)(qp + d4);
        #pragma unroll
        for (int d = 0; d < 32; d++) {
            float cs = g_cos[i * 32 + d], sn = g_sin[i * 32 + d];
            qv[d]      = f2tff((raw[d] * cs - raw[d + 32] * sn) * 0.125f);
            qv[d + 32] = f2tff((raw[d + 32] * cs + raw[d] * sn) * 0.125f);
        }
        #pragma unroll
        for (int bb = 0; bb < 4; bb++)
            #pragma unroll
            for (int tg = 0; tg < 4; tg++) {
                float4 f = {qv[bb*16+tg], qv[bb*16+tg+4], qv[bb*16+tg+8], qv[bb*16+tg+12]};
                *(float4*)&QPs[r * QP_ST + bb * 16 + tg * 4] = f;
            }
    }
    __syncthreads();

    unsigned qa[8][4];
    {
        int rA = wm * 16 + gid, rB = rA + 8;
        #pragma unroll
        for (int bb = 0; bb < 4; bb++) {
            float4 lo = *(const float4*)&QPs[rA * QP_ST + bb * 16 + tig * 4];
            float4 hi = *(const float4*)&QPs[rB * QP_ST + bb * 16 + tig * 4];
            qa[2*bb][0]   = __float_as_uint(lo.x); qa[2*bb][1]   = __float_as_uint(hi.x);
            qa[2*bb][2]   = __float_as_uint(lo.y); qa[2*bb][3]   = __float_as_uint(hi.y);
            qa[2*bb+1][0] = __float_as_uint(lo.z); qa[2*bb+1][1] = __float_as_uint(hi.z);
            qa[2*bb+1][2] = __float_as_uint(lo.w); qa[2*bb+1][3] = __float_as_uint(hi.w);
        }
    }

    float O[8][4];
    #pragma unroll
    for (int nf = 0; nf < 8; nf++)
        #pragma unroll
        for (int e = 0; e < 4; e++) O[nf][e] = 0.f;
    float m0 = -1e30f, m1 = -1e30f, l0 = 0.f, l1 = 0.f;

    float* Ps = QPs + (size_t)(wm * 16) * QP_ST;
    int Imin = qbase + wm * 16;       // smallest query row of this warp
    int Imax = Imin + 15;             // largest
    int i0 = Imin + gid;
    int i1 = i0 + 8;

    int clo = wm >> 2, chi = clo + 2;
    if (w == 0) clo = 2;

    for (int c = clo; c <= chi; c++) {
        int jbase = qbase - WW + c * 64;
        float S[8][4];
        #pragma unroll
        for (int nf = 0; nf < 8; nf++)
            #pragma unroll
            for (int e = 0; e < 4; e++) S[nf][e] = 0.f;
        #pragma unroll
        for (int nf = 0; nf < 8; nf++) {
            int jlo = jbase + nf * 8;
            // warp-uniform skip: frag fully in the future, or fully older than window
            if (jlo > Imax || jlo + 7 < Imin - WW) continue;
            int n = c * 64 + nf * 8 + gid;
            #pragma unroll
            for (int bb = 0; bb < 4; bb++) {
                float4 f = *(const float4*)&Ks2[n * KS2_ST + bb * 16 + tig * 4];
                mma_tf32(S[nf], qa[2*bb][0], qa[2*bb][1], qa[2*bb][2], qa[2*bb][3],
                         __float_as_uint(f.x), __float_as_uint(f.y));
                mma_tf32(S[nf], qa[2*bb+1][0], qa[2*bb+1][1], qa[2*bb+1][2], qa[2*bb+1][3],
                         __float_as_uint(f.z), __float_as_uint(f.w));
            }
        }
        float rmax0 = -1e30f, rmax1 = -1e30f;
        #pragma unroll
        for (int nf = 0; nf < 8; nf++) {
            int j0 = jbase + nf * 8 + 2 * tig;
            if (i0 < j0     || i0 - j0 > WW)     S[nf][0] = -1e9f;
            if (i0 < j0 + 1 || i0 - j0 - 1 > WW) S[nf][1] = -1e9f;
            if (i1 < j0     || i1 - j0 > WW)     S[nf][2] = -1e9f;
            if (i1 < j0 + 1 || i1 - j0 - 1 > WW) S[nf][3] = -1e9f;
            rmax0 = fmaxf(rmax0, fmaxf(S[nf][0], S[nf][1]));
            rmax1 = fmaxf(rmax1, fmaxf(S[nf][2], S[nf][3]));
        }
        rmax0 = fmaxf(rmax0, __shfl_xor_sync(0xffffffffu, rmax0, 1));
        rmax0 = fmaxf(rmax0, __shfl_xor_sync(0xffffffffu, rmax0, 2));
        rmax1 = fmaxf(rmax1, __shfl_xor_sync(0xffffffffu, rmax1, 1));
        rmax1 = fmaxf(rmax1, __shfl_xor_sync(0xffffffffu, rmax1, 2));
        float mn0 = fmaxf(m0, rmax0), mn1 = fmaxf(m1, rmax1);
        float cor0 = __expf(m0 - mn0), cor1 = __expf(m1 - mn1);
        m0 = mn0; m1 = mn1;
        float ls0 = 0.f, ls1 = 0.f;
        #pragma unroll
        for (int nf = 0; nf < 8; nf++) {
            float p0 = __expf(S[nf][0] - mn0);
            float p1 = __expf(S[nf][1] - mn0);
            float p2 = __expf(S[nf][2] - mn1);
            float p3 = __expf(S[nf][3] - mn1);
            ls0 += p0 + p1;
            ls1 += p2 + p3;
            int n0 = nf * 8 + 2 * tig;
            int n1 = n0 + 1;
            int cp0 = (n0 >> 4) * 16 + ((n0 & 15) & 3) * 4 + ((n0 & 15) >> 2);
            int cp1 = (n1 >> 4) * 16 + ((n1 & 15) & 3) * 4 + ((n1 & 15) >> 2);
            Ps[gid * QP_ST + cp0]       = f2tff(p0);
            Ps[gid * QP_ST + cp1]       = f2tff(p1);
            Ps[(gid + 8) * QP_ST + cp0] = f2tff(p2);
            Ps[(gid + 8) * QP_ST + cp1] = f2tff(p3);
        }
        l0 = l0 * cor0 + ls0;
        l1 = l1 * cor1 + ls1;
        #pragma unroll
        for (int nf = 0; nf < 8; nf++) {
            O[nf][0] *= cor0; O[nf][1] *= cor0;
            O[nf][2] *= cor1; O[nf][3] *= cor1;
        }
        __syncwarp();
        unsigned pa[8][4];
        #pragma unroll
        for (int bb = 0; bb < 4; bb++) {
            float4 lo = *(const float4*)&Ps[gid * QP_ST + bb * 16 + tig * 4];
            float4 hi = *(const float4*)&Ps[(gid + 8) * QP_ST + bb * 16 + tig * 4];
            pa[2*bb][0]   = __float_as_uint(lo.x); pa[2*bb][1]   = __float_as_uint(hi.x);
            pa[2*bb][2]   = __float_as_uint(lo.y); pa[2*bb][3]   = __float_as_uint(hi.y);
            pa[2*bb+1][0] = __float_as_uint(lo.z); pa[2*bb+1][1] = __float_as_uint(hi.z);
            pa[2*bb+1][2] = __float_as_uint(lo.w); pa[2*bb+1][3] = __float_as_uint(hi.w);
        }
        #pragma unroll
        for (int nd = 0; nd < 8; nd++) {
            int n = nd * 8 + gid;
            #pragma unroll
            for (int bb = 0; bb < 4; bb++) {
                // skip k-blocks (16 keys) whose P is exactly zero (fully masked)
                int jbl = jbase + bb * 16;
                if (jbl > Imax || jbl + 15 < Imin - WW) continue;
                float4 f = *(const float4*)&Vs2[n * VS2_ST + c * 64 + bb * 16 + tig * 4];
                mma_tf32(O[nd], pa[2*bb][0], pa[2*bb][1], pa[2*bb][2], pa[2*bb][3],
                         __float_as_uint(f.x), __float_as_uint(f.y));
                mma_tf32(O[nd], pa[2*bb+1][0], pa[2*bb+1][1], pa[2*bb+1][2], pa[2*bb+1][3],
                         __float_as_uint(f.z), __float_as_uint(f.w));
            }
        }
        __syncwarp();
    }

    l0 += __shfl_xor_sync(0xffffffffu, l0, 1);
    l0 += __shfl_xor_sync(0xffffffffu, l0, 2);
    l1 += __shfl_xor_sync(0xffffffffu, l1, 1);
    l1 += __shfl_xor_sync(0xffffffffu, l1, 2);
    float inv0 = 1.f / l0, inv1 = 1.f / l1;

    float* op0 = outp + (rowbase + i0) * INNER + head * DH;
    float* op1 = outp + (rowbase + i1) * INNER + head * DH;
    #pragma unroll
    for (int nd = 0; nd < 8; nd++) {
        int d0 = nd * 8 + 2 * tig;
        op0[d0]     = f2tff(O[nd][0] * inv0);
        op0[d0 + 1] = f2tff(O[nd][1] * inv0);
        op1[d0]     = f2tff(O[nd][2] * inv1);
        op1[d0 + 1] = f2tff(O[nd][3] * inv1);
    }
}

// ---------------- Final LN + logits + slice ----------------
__global__ void final_kernel(const float* __restrict__ gg, const float* __restrict__ bb,
                             const float* __restrict__ wl, float* __restrict__ out) {
    int row = blockIdx.x, c = threadIdx.x;
    int n = row & (N_ - 1);
    if (n < SLACK || n >= N_ - SLACK) return;
    float v = g_h[(size_t)row * LD + c];
    __shared__ float sh[16];
    __shared__ float stat[2];
    float s = v, sq = v * v;
    #pragma unroll
    for (int o = 16; o > 0; o >>= 1) {
        s  += __shfl_down_sync(0xffffffffu, s, o);
        sq += __shfl_down_sync(0xffffffffu, sq, o);
    }
    if ((c & 31) == 0) { sh[c >> 5] = s; sh[8 + (c >> 5)] = sq; }
    __syncthreads();
    if (c == 0) {
        float S = 0.f, SQ = 0.f;
        #pragma unroll
        for (int i = 0; i < 8; i++) { S += sh[i]; SQ += sh[8 + i]; }
        float mean = S * (1.f / LD);
        stat[0] = mean;
        stat[1] = rsqrtf(SQ * (1.f / LD) - mean * mean + 1e-5f);
    }
    __syncthreads();
    float contrib = ((v - stat[0]) * stat[1] * gg[c] + bb[c]) * wl[c];
    #pragma unroll
    for (int o = 16; o > 0; o >>= 1)
        contrib += __shfl_down_sync(0xffffffffu, contrib, o);
    __syncthreads();
    if ((c & 31) == 0) sh[c >> 5] = contrib;
    __syncthreads();
    if (c == 0) {
        float T = 0.f;
        #pragma unroll
        for (int i = 0; i < 8; i++) T += sh[i];
        int bidx = row >> 12;
        out[bidx * (N_ - 2 * SLACK) + (n - SLACK)] = T;
    }
}

// ---------------- Launch ----------------
extern "C" void kernel_launch(void* const* d_in, const int* in_sizes, int n_in,
                              void* d_out, int out_size) {
    const float* x        = (const float*)d_in[0];
    const float* W_exp    = (const float*)d_in[1];
    const float* b_exp    = (const float*)d_in[2];
    const float* pos_emb  = (const float*)d_in[3];
    const float* ln_att_g = (const float*)d_in[4];
    const float* ln_att_b = (const float*)d_in[5];
    const float* Wqkv     = (const float*)d_in[6];
    const float* Wout     = (const float*)d_in[7];
    const float* ln_ff_g  = (const float*)d_in[8];
    const float* ln_ff_b  = (const float*)d_in[9];
    const float* W1       = (const float*)d_in[10];
    const float* b1       = (const float*)d_in[11];
    const float* W2       = (const float*)d_in[12];
    const float* b2       = (const float*)d_in[13];
    const float* ln_f_g   = (const float*)d_in[14];
    const float* ln_f_b   = (const float*)d_in[15];
    const float* W_logits = (const float*)d_in[16];
    float* out = (float*)d_out;

    float *ph, *py, *pqkv, *po, *pff, *pwr;
    cudaGetSymbolAddress((void**)&ph,   g_h);
    cudaGetSymbolAddress((void**)&py,   g_y);
    cudaGetSymbolAddress((void**)&pqkv, g_qkv);
    cudaGetSymbolAddress((void**)&po,   g_o);
    cudaGetSymbolAddress((void**)&pff,  g_ff);
    cudaGetSymbolAddress((void**)&pwr,  g_wr);

    cudaFuncSetAttribute(attn_mma_kernel, cudaFuncAttributeMaxDynamicSharedMemorySize, ATTN_SMEM);
    cudaFuncSetAttribute(tgemm<0>, cudaFuncAttributeMaxDynamicSharedMemorySize, TG_SMEM);
    cudaFuncSetAttribute(tgemm<1>, cudaFuncAttributeMaxDynamicSharedMemorySize, TG_SMEM);
    cudaFuncSetAttribute(tgemm<2>, cudaFuncAttributeMaxDynamicSharedMemorySize, TG_SMEM);
    cudaFuncSetAttribute(tgemm<3>, cudaFuncAttributeMaxDynamicSharedMemorySize, TG_SMEM);

    rope_table_kernel<<<(N_ * 32 + 255) / 256, 256>>>();
    round_tf32_kernel<<<(DEPTH*LD*QKVW + 255)/256, 256>>>(Wqkv, pwr + WQKV_OFF, DEPTH*LD*QKVW);
    round_tf32_kernel<<<(DEPTH*INNER*LD + 255)/256, 256>>>(Wout, pwr + WOUT_OFF, DEPTH*INNER*LD);
    round_tf32_kernel<<<(DEPTH*LD*FF + 255)/256, 256>>>(W1, pwr + W1_OFF, DEPTH*LD*FF);
    round_tf32_kernel<<<(DEPTH*FF*LD + 255)/256, 256>>>(W2, pwr + W2_OFF, DEPTH*FF*LD);
    expand_kernel<<<R_, LD>>>(x, W_exp, b_exp, pos_emb);

    for (int l = 0; l < DEPTH; ++l) {
        ln_kernel<<<R_, LD>>>(ph, py, ln_att_g + l * LD, ln_att_b + l * LD);
        tgemm<0><<<dim3(QKVW / 128, R_ / 128), 256, TG_SMEM>>>(
            py, pwr + WQKV_OFF + (size_t)l * LD * QKVW, pqkv, nullptr, R_, QKVW, LD);
        attn_mma_kernel<<<dim3(N_ / WW, H_, B_), 256, ATTN_SMEM>>>(pqkv, po);
        tgemm<2><<<dim3(LD / 128, R_ / 128), 256, TG_SMEM>>>(
            po, pwr + WOUT_OFF + (size_t)l * INNER * LD, ph, nullptr, R_, LD, INNER);
        ln_kernel<<<R_, LD>>>(ph, py, ln_ff_g + l * LD, ln_ff_b + l * LD);
        tgemm<1><<<dim3(FF / 128, R_ / 128), 256, TG_SMEM>>>(
            py, pwr + W1_OFF + (size_t)l * LD * FF, pff, b1 + (size_t)l * FF, R_, FF, LD);
        tgemm<3><<<dim3(LD / 128, R_ / 128), 256, TG_SMEM>>>(
            pff, pwr + W2_OFF + (size_t)l * FF * LD, ph, b2 + (size_t)l * LD, R_, LD, FF);
    }

    final_kernel<<<R_, LD>>>(ln_f_g, ln_f_b, W_logits, out);
}

// round 7
// speedup vs baseline: 2.9385x; 1.3494x over previous
#include <cuda_runtime.h>
#include <cuda_fp16.h>
#include <math.h>

// ---------------- Problem constants ----------------
constexpr int B_    = 16;
constexpr int N_    = 4096;
constexpr int LD    = 256;
constexpr int H_    = 8;
constexpr int DH    = 64;
constexpr int WW    = 128;
constexpr int INNER = 512;   // H_*DH
constexpr int DEPTH = 4;
constexpr int FF    = 1024;
constexpr int SLACK = 50;
constexpr int R_    = B_ * N_;          // 65536 rows
constexpr int QKVW  = 3 * INNER;        // 1536

// ---------------- Scratch ----------------
__device__ float  g_h[(size_t)R_ * LD];          // fp32 residual stream
__device__ __half g_yh[(size_t)R_ * LD];         // LN output (GEMM A)
__device__ __half g_qkvh[(size_t)R_ * QKVW];     // qkv fp16
__device__ __half g_oh[(size_t)R_ * INNER];      // attention out fp16
__device__ __half g_ffh[(size_t)R_ * FF];        // FF hidden fp16
__device__ unsigned g_wp[2097152];               // k-pair-packed fp16 weights
__device__ float  g_cos[(size_t)N_ * 32];
__device__ float  g_sin[(size_t)N_ * 32];
// word offsets into g_wp
constexpr size_t WQKV_OFF = 0;
constexpr size_t WOUT_OFF = 786432;
constexpr size_t W1_OFF   = 1048576;
constexpr size_t W2_OFF   = 1572864;

__device__ __forceinline__ unsigned packh2(float lo, float hi) {
    __half2 h = __floats2half2_rn(lo, hi);
    return *reinterpret_cast<unsigned*>(&h);
}

__device__ __forceinline__ void mma_f16(float* c, unsigned a0, unsigned a1,
                                        unsigned a2, unsigned a3,
                                        unsigned b0, unsigned b1) {
    asm volatile("mma.sync.aligned.m16n8k16.row.col.f32.f16.f16.f32 "
                 "{%0,%1,%2,%3}, {%4,%5,%6,%7}, {%8,%9}, {%0,%1,%2,%3};\n"
                 : "+f"(c[0]), "+f"(c[1]), "+f"(c[2]), "+f"(c[3])
                 : "r"(a0), "r"(a1), "r"(a2), "r"(a3), "r"(b0), "r"(b1));
}

__device__ __forceinline__ void cp16(void* smem, const void* g) {
    unsigned sa = (unsigned)__cvta_generic_to_shared(smem);
    asm volatile("cp.async.ca.shared.global [%0], [%1], 16;\n" :: "r"(sa), "l"(g));
}

// ---------------- RoPE table ----------------
__global__ void rope_table_kernel() {
    int idx = blockIdx.x * blockDim.x + threadIdx.x;
    if (idx >= N_ * 32) return;
    int n = idx >> 5, d = idx & 31;
    float invf = (float)(1.0 / pow(10000.0, (double)(2 * d) / 64.0));
    float angf = (float)n * invf;
    double a = (double)angf;
    g_cos[idx] = (float)cos(a);
    g_sin[idx] = (float)sin(a);
}

// ---------------- weight packing: W[K][N] fp32 -> out[K/2][N] half2-words ----------------
__global__ void pack_w_kernel(const float* __restrict__ W, unsigned* __restrict__ out,
                              int rows2, int N) {
    int idx = blockIdx.x * blockDim.x + threadIdx.x;
    if (idx >= rows2 * N) return;
    int kp = idx / N, n = idx - kp * N;
    out[idx] = packh2(W[(size_t)(2 * kp) * N + n], W[(size_t)(2 * kp + 1) * N + n]);
}

// ---------------- Expand ----------------
__global__ void expand_kernel(const float* __restrict__ x, const float* __restrict__ We,
                              const float* __restrict__ be, const float* __restrict__ pe) {
    int row = blockIdx.x;
    int c   = threadIdx.x;
    int n   = row & (N_ - 1);
    float x0 = x[row * 2 + 0], x1 = x[row * 2 + 1];
    g_h[(size_t)row * LD + c] = x0 * We[c] + x1 * We[LD + c] + be[c] + pe[n * LD + c];
}

// ---------------- LayerNorm (fp32 in, fp16 out) ----------------
__global__ void ln_kernel(const float* __restrict__ src, __half* __restrict__ dst,
                          const float* __restrict__ gg, const float* __restrict__ bb) {
    int row = blockIdx.x, c = threadIdx.x;
    float v = src[(size_t)row * LD + c];
    float s = v, sq = v * v;
    #pragma unroll
    for (int o = 16; o > 0; o >>= 1) {
        s  += __shfl_down_sync(0xffffffffu, s, o);
        sq += __shfl_down_sync(0xffffffffu, sq, o);
    }
    __shared__ float sh[16];
    __shared__ float stat[2];
    if ((c & 31) == 0) { sh[c >> 5] = s; sh[8 + (c >> 5)] = sq; }
    __syncthreads();
    if (c == 0) {
        float S = 0.f, SQ = 0.f;
        #pragma unroll
        for (int i = 0; i < 8; i++) { S += sh[i]; SQ += sh[8 + i]; }
        float mean = S * (1.f / LD);
        stat[0] = mean;
        stat[1] = rsqrtf(SQ * (1.f / LD) - mean * mean + 1e-5f);
    }
    __syncthreads();
    dst[(size_t)row * LD + c] = __float2half_rn((v - stat[0]) * stat[1] * gg[c] + bb[c]);
}

// ---------------- fp16 GEMM: BK=32, m16n8k16, 3-stage cp.async ----------------
// A: fp16 k-major [M][K]; B: packed words [K/2][N].
// EPI: 0 = half store, 1 = +bias, GELU, half store, 2 = fp32 C += AB, 3 = fp32 C += AB + bias
constexpr int AST = 20;    // words per A smem row (16 + 4 pad; 80B, 16B-aligned)
constexpr int BST = 132;   // words per B smem row (128 + 4 pad)
constexpr int HG_STAGES = 3;
constexpr int AS_W = 128 * AST;    // words per A stage
constexpr int BS_W = 16 * BST;     // words per B stage
constexpr int HG_SMEM = HG_STAGES * (AS_W + BS_W) * 4;   // 56064 B

template <int EPI>
__global__ __launch_bounds__(256, 2)
void hgemm(const __half* __restrict__ A, const unsigned* __restrict__ Bp,
           void* __restrict__ Cv, const float* __restrict__ bias, int Nc, int K) {
    extern __shared__ unsigned smw[];
    unsigned* AsBase = smw;
    unsigned* BsBase = smw + HG_STAGES * AS_W;

    int tid  = threadIdx.x;
    int row0 = blockIdx.y * 128;
    int col0 = blockIdx.x * 128;
    int lane = tid & 31, w = tid >> 5;
    int gid  = lane >> 2, tig = lane & 3;
    int wr   = w & 1;
    int wc   = w >> 1;

    int ar = tid >> 1;        // 0..127 A row
    int ac = tid & 1;         // chunk parity: chunks {ac, ac+2} of 4 x 16B
    int bk = tid >> 5;        // 0..7 B kp-row (+8 second)
    int bc = tid & 31;        // 4-word group

    const __half* ApS = A + (size_t)(row0 + ar) * K;
    const unsigned* BpS = Bp + (size_t)bk * Nc + col0 + bc * 4;

    float acc[4][4][4];
    #pragma unroll
    for (int mi = 0; mi < 4; mi++)
        #pragma unroll
        for (int ni = 0; ni < 4; ni++)
            #pragma unroll
            for (int e = 0; e < 4; e++) acc[mi][ni][e] = 0.f;

    int NT = K >> 5;   // k=32 per iter

    auto stage = [&](int kti, int buf) {
        unsigned* Asb = AsBase + buf * AS_W;
        unsigned* Bsb = BsBase + buf * BS_W;
        const __half* as = ApS + kti * 32 + ac * 8;
        cp16(&Asb[ar * AST + ac * 4], as);
        cp16(&Asb[ar * AST + ac * 4 + 8], as + 16);
        const unsigned* bs = BpS + (size_t)kti * 16 * Nc;
        cp16(&Bsb[bk * BST + bc * 4], bs);
        cp16(&Bsb[(bk + 8) * BST + bc * 4], bs + (size_t)8 * Nc);
    };

    stage(0, 0);
    asm volatile("cp.async.commit_group;\n");
    stage(1, 1);
    asm volatile("cp.async.commit_group;\n");

    for (int it = 0; it < NT; it++) {
        int cur = it % HG_STAGES;
        asm volatile("cp.async.wait_group 1;\n");
        __syncthreads();
        if (it + 2 < NT) stage(it + 2, (it + 2) % HG_STAGES);
        asm volatile("cp.async.commit_group;\n");

        const unsigned* Asb = AsBase + cur * AS_W;
        const unsigned* Bsb = BsBase + cur * BS_W;

        #pragma unroll
        for (int s = 0; s < 2; s++) {
            uint2 fA[4][2];
            #pragma unroll
            for (int mi = 0; mi < 4; mi++) {
                int m = wr * 64 + mi * 16 + gid;
                fA[mi][0] = *(const uint2*)&Asb[m * AST + s * 8 + 2 * tig];
                fA[mi][1] = *(const uint2*)&Asb[(m + 8) * AST + s * 8 + 2 * tig];
            }
            #pragma unroll
            for (int ni = 0; ni < 4; ni++) {
                int n = wc * 32 + ni * 8 + gid;
                unsigned b0 = Bsb[(s * 8 + 2 * tig) * BST + n];
                unsigned b1 = Bsb[(s * 8 + 2 * tig + 1) * BST + n];
                #pragma unroll
                for (int mi = 0; mi < 4; mi++) {
                    mma_f16(acc[mi][ni], fA[mi][0].x, fA[mi][1].x,
                            fA[mi][0].y, fA[mi][1].y, b0, b1);
                }
            }
        }
    }

    __half* Ch = (__half*)Cv;
    float*  Cf = (float*)Cv;
    #pragma unroll
    for (int mi = 0; mi < 4; mi++) {
        int ra = row0 + wr * 64 + mi * 16 + gid;
        #pragma unroll
        for (int ni = 0; ni < 4; ni++) {
            int cc = col0 + wc * 32 + ni * 8 + tig * 2;
            #pragma unroll
            for (int half = 0; half < 2; half++) {
                int r = ra + half * 8;
                float v0 = acc[mi][ni][half * 2 + 0];
                float v1 = acc[mi][ni][half * 2 + 1];
                size_t off = (size_t)r * Nc + cc;
                if (EPI == 0) {
                    *(__half2*)&Ch[off] = __floats2half2_rn(v0, v1);
                } else if (EPI == 1) {
                    v0 += bias[cc];
                    v1 += bias[cc + 1];
                    v0 = 0.5f * v0 * (1.f + erff(v0 * 0.70710678118654752f));
                    v1 = 0.5f * v1 * (1.f + erff(v1 * 0.70710678118654752f));
                    *(__half2*)&Ch[off] = __floats2half2_rn(v0, v1);
                } else if (EPI == 2) {
                    Cf[off]     += v0;
                    Cf[off + 1] += v1;
                } else {
                    Cf[off]     += v0 + bias[cc];
                    Cf[off + 1] += v1 + bias[cc + 1];
                }
            }
        }
    }
}

// ---------------- fp16 tensor-core flash local attention ----------------
// smem word layout (pair-packed half2 words):
//  Ks[32 dp][260]  : (K[jj][2dp],K[jj][2dp+1])       (k-dim = d for S)
//  Qs[128 r][34]   : (Q[r][2dp],Q[r][2dp+1])
//  Vs[128 jp][68]  : (V[2jp][d],V[2jp+1][d])         (k-dim = jj for PV)
//  Ps[8 warps][16 r][36]
constexpr int KST = 260;
constexpr int QST = 34;
constexpr int VST = 68;
constexpr int PST = 36;
constexpr int KS_OFF = 0;
constexpr int QS_OFF = 32 * KST;                // 8320
constexpr int VS_OFF = QS_OFF + 128 * QST;     // 12672
constexpr int PS_OFF = VS_OFF + 128 * VST;     // 21376
constexpr int ATTN_SMEM = (PS_OFF + 8 * 16 * PST) * 4;   // 103936 B

__global__ __launch_bounds__(256)
void attn_mma_kernel(const __half* __restrict__ qkv, __half* __restrict__ outp) {
    extern __shared__ unsigned smU[];

    int w = blockIdx.x, head = blockIdx.y, b = blockIdx.z;
    int tid  = threadIdx.x;
    int lane = tid & 31;
    int wm   = tid >> 5;
    int gid  = lane >> 2, tig = lane & 3;
    int qbase = w * WW;
    size_t rowbase = (size_t)b * N_;

    // ---- stage K (rotary), thread jj = tid ----
    {
        int jj = tid;
        int p = qbase - WW + jj;
        float kv[64];
        if (p >= 0) {
            const __half2* kp2 = (const __half2*)(qkv + (rowbase + p) * QKVW + INNER + head * DH);
            float raw[64];
            #pragma unroll
            for (int i = 0; i < 32; i++) {
                float2 f = __half22float2(kp2[i]);
                raw[2 * i] = f.x; raw[2 * i + 1] = f.y;
            }
            #pragma unroll
            for (int d = 0; d < 32; d++) {
                float cs = g_cos[p * 32 + d], sn = g_sin[p * 32 + d];
                kv[d]      = raw[d] * cs - raw[d + 32] * sn;
                kv[d + 32] = raw[d + 32] * cs + raw[d] * sn;
            }
        } else {
            #pragma unroll
            for (int d = 0; d < 64; d++) kv[d] = 0.f;
        }
        #pragma unroll
        for (int dp = 0; dp < 32; dp++)
            smU[KS_OFF + dp * KST + jj] = packh2(kv[2 * dp], kv[2 * dp + 1]);
    }
    // ---- stage V: thread covers row-pair jp = tid>>1, half of d ----
    {
        int jp = tid >> 1;
        int dh = (tid & 1) * 32;
        int p0 = qbase - WW + 2 * jp;
        unsigned* vrow = smU + VS_OFF + jp * VST + dh;
        if (p0 >= 0) {
            const __half2* vA = (const __half2*)(qkv + (rowbase + p0) * QKVW + 2 * INNER + head * DH + dh);
            const __half2* vB = (const __half2*)(qkv + (rowbase + p0 + 1) * QKVW + 2 * INNER + head * DH + dh);
            #pragma unroll
            for (int i = 0; i < 16; i++) {
                float2 fa = __half22float2(vA[i]);
                float2 fb = __half22float2(vB[i]);
                vrow[2 * i]     = packh2(fa.x, fb.x);
                vrow[2 * i + 1] = packh2(fa.y, fb.y);
            }
        } else {
            #pragma unroll
            for (int i = 0; i < 32; i++) vrow[i] = 0u;
        }
    }
    // ---- stage Q (rotary + scale), threads 0..127 ----
    if (tid < 128) {
        int r = tid;
        int i = qbase + r;
        const __half2* qp2 = (const __half2*)(qkv + (rowbase + i) * QKVW + head * DH);
        float raw[64], qv[64];
        #pragma unroll
        for (int ii = 0; ii < 32; ii++) {
            float2 f = __half22float2(qp2[ii]);
            raw[2 * ii] = f.x; raw[2 * ii + 1] = f.y;
        }
        #pragma unroll
        for (int d = 0; d < 32; d++) {
            float cs = g_cos[i * 32 + d], sn = g_sin[i * 32 + d];
            qv[d]      = (raw[d] * cs - raw[d + 32] * sn) * 0.125f;
            qv[d + 32] = (raw[d + 32] * cs + raw[d] * sn) * 0.125f;
        }
        #pragma unroll
        for (int j = 0; j < 32; j++)
            smU[QS_OFF + r * QST + j] = packh2(qv[2 * j], qv[2 * j + 1]);
    }
    __syncthreads();

    // ---- Q fragments ----
    unsigned qa[4][4];
    {
        int rA = wm * 16 + gid, rB = rA + 8;
        #pragma unroll
        for (int s = 0; s < 4; s++) {
            uint2 u0 = *(const uint2*)&smU[QS_OFF + rA * QST + s * 8 + 2 * tig];
            uint2 u1 = *(const uint2*)&smU[QS_OFF + rB * QST + s * 8 + 2 * tig];
            qa[s][0] = u0.x; qa[s][1] = u1.x; qa[s][2] = u0.y; qa[s][3] = u1.y;
        }
    }

    float O[8][4];
    #pragma unroll
    for (int nf = 0; nf < 8; nf++)
        #pragma unroll
        for (int e = 0; e < 4; e++) O[nf][e] = 0.f;
    float m0 = -1e30f, m1 = -1e30f, l0 = 0.f, l1 = 0.f;

    unsigned* Ps = smU + PS_OFF + wm * 16 * PST;
    int Imin = qbase + wm * 16;
    int Imax = Imin + 15;
    int i0 = Imin + gid;
    int i1 = i0 + 8;

    int clo = wm >> 2, chi = clo + 2;
    if (w == 0) clo = 2;

    for (int c = clo; c <= chi; c++) {
        int jbase = qbase - WW + c * 64;
        float S[8][4];
        #pragma unroll
        for (int nf = 0; nf < 8; nf++)
            #pragma unroll
            for (int e = 0; e < 4; e++) S[nf][e] = 0.f;
        #pragma unroll
        for (int nf = 0; nf < 8; nf++) {
            int jlo = jbase + nf * 8;
            if (jlo > Imax || jlo + 7 < Imin - WW) continue;
            int n = c * 64 + nf * 8 + gid;
            #pragma unroll
            for (int s = 0; s < 4; s++) {
                unsigned b0 = smU[KS_OFF + (s * 8 + 2 * tig) * KST + n];
                unsigned b1 = smU[KS_OFF + (s * 8 + 2 * tig + 1) * KST + n];
                mma_f16(S[nf], qa[s][0], qa[s][1], qa[s][2], qa[s][3], b0, b1);
            }
        }
        float rmax0 = -1e30f, rmax1 = -1e30f;
        #pragma unroll
        for (int nf = 0; nf < 8; nf++) {
            int j0 = jbase + nf * 8 + 2 * tig;
            if (i0 < j0     || i0 - j0 > WW)     S[nf][0] = -1e9f;
            if (i0 < j0 + 1 || i0 - j0 - 1 > WW) S[nf][1] = -1e9f;
            if (i1 < j0     || i1 - j0 > WW)     S[nf][2] = -1e9f;
            if (i1 < j0 + 1 || i1 - j0 - 1 > WW) S[nf][3] = -1e9f;
            rmax0 = fmaxf(rmax0, fmaxf(S[nf][0], S[nf][1]));
            rmax1 = fmaxf(rmax1, fmaxf(S[nf][2], S[nf][3]));
        }
        rmax0 = fmaxf(rmax0, __shfl_xor_sync(0xffffffffu, rmax0, 1));
        rmax0 = fmaxf(rmax0, __shfl_xor_sync(0xffffffffu, rmax0, 2));
        rmax1 = fmaxf(rmax1, __shfl_xor_sync(0xffffffffu, rmax1, 1));
        rmax1 = fmaxf(rmax1, __shfl_xor_sync(0xffffffffu, rmax1, 2));
        float mn0 = fmaxf(m0, rmax0), mn1 = fmaxf(m1, rmax1);
        float cor0 = __expf(m0 - mn0), cor1 = __expf(m1 - mn1);
        m0 = mn0; m1 = mn1;
        float ls0 = 0.f, ls1 = 0.f;
        #pragma unroll
        for (int nf = 0; nf < 8; nf++) {
            float p0 = __expf(S[nf][0] - mn0);
            float p1 = __expf(S[nf][1] - mn0);
            float p2 = __expf(S[nf][2] - mn1);
            float p3 = __expf(S[nf][3] - mn1);
            ls0 += p0 + p1;
            ls1 += p2 + p3;
            int jp = nf * 4 + tig;   // jj-pair index (jj = nf*8 + 2tig)
            Ps[gid * PST + jp]       = packh2(p0, p1);
            Ps[(gid + 8) * PST + jp] = packh2(p2, p3);
        }
        l0 = l0 * cor0 + ls0;
        l1 = l1 * cor1 + ls1;
        #pragma unroll
        for (int nf = 0; nf < 8; nf++) {
            O[nf][0] *= cor0; O[nf][1] *= cor0;
            O[nf][2] *= cor1; O[nf][3] *= cor1;
        }
        __syncwarp();
        unsigned pa[4][4];
        #pragma unroll
        for (int s = 0; s < 4; s++) {
            uint2 u0 = *(const uint2*)&Ps[gid * PST + s * 8 + 2 * tig];
            uint2 u1 = *(const uint2*)&Ps[(gid + 8) * PST + s * 8 + 2 * tig];
            pa[s][0] = u0.x; pa[s][1] = u1.x; pa[s][2] = u0.y; pa[s][3] = u1.y;
        }
        #pragma unroll
        for (int nd = 0; nd < 8; nd++) {
            int n = nd * 8 + gid;
            #pragma unroll
            for (int s = 0; s < 4; s++) {
                int jbl = jbase + s * 16;
                if (jbl > Imax || jbl + 15 < Imin - WW) continue;
                unsigned b0 = smU[VS_OFF + (c * 32 + s * 8 + 2 * tig) * VST + n];
                unsigned b1 = smU[VS_OFF + (c * 32 + s * 8 + 2 * tig + 1) * VST + n];
                mma_f16(O[nd], pa[s][0], pa[s][1], pa[s][2], pa[s][3], b0, b1);
            }
        }
        __syncwarp();
    }

    l0 += __shfl_xor_sync(0xffffffffu, l0, 1);
    l0 += __shfl_xor_sync(0xffffffffu, l0, 2);
    l1 += __shfl_xor_sync(0xffffffffu, l1, 1);
    l1 += __shfl_xor_sync(0xffffffffu, l1, 2);
    float inv0 = 1.f / l0, inv1 = 1.f / l1;

    __half* op0 = outp + (rowbase + i0) * INNER + head * DH;
    __half* op1 = outp + (rowbase + i1) * INNER + head * DH;
    #pragma unroll
    for (int nd = 0; nd < 8; nd++) {
        int d0 = nd * 8 + 2 * tig;
        *(__half2*)&op0[d0] = __floats2half2_rn(O[nd][0] * inv0, O[nd][1] * inv0);
        *(__half2*)&op1[d0] = __floats2half2_rn(O[nd][2] * inv1, O[nd][3] * inv1);
    }
}

// ---------------- Final LN + logits + slice ----------------
__global__ void final_kernel(const float* __restrict__ gg, const float* __restrict__ bb,
                             const float* __restrict__ wl, float* __restrict__ out) {
    int row = blockIdx.x, c = threadIdx.x;
    int n = row & (N_ - 1);
    if (n < SLACK || n >= N_ - SLACK) return;
    float v = g_h[(size_t)row * LD + c];
    __shared__ float sh[16];
    __shared__ float stat[2];
    float s = v, sq = v * v;
    #pragma unroll
    for (int o = 16; o > 0; o >>= 1) {
        s  += __shfl_down_sync(0xffffffffu, s, o);
        sq += __shfl_down_sync(0xffffffffu, sq, o);
    }
    if ((c & 31) == 0) { sh[c >> 5] = s; sh[8 + (c >> 5)] = sq; }
    __syncthreads();
    if (c == 0) {
        float S = 0.f, SQ = 0.f;
        #pragma unroll
        for (int i = 0; i < 8; i++) { S += sh[i]; SQ += sh[8 + i]; }
        float mean = S * (1.f / LD);
        stat[0] = mean;
        stat[1] = rsqrtf(SQ * (1.f / LD) - mean * mean + 1e-5f);
    }
    __syncthreads();
    float contrib = ((v - stat[0]) * stat[1] * gg[c] + bb[c]) * wl[c];
    #pragma unroll
    for (int o = 16; o > 0; o >>= 1)
        contrib += __shfl_down_sync(0xffffffffu, contrib, o);
    __syncthreads();
    if ((c & 31) == 0) sh[c >> 5] = contrib;
    __syncthreads();
    if (c == 0) {
        float T = 0.f;
        #pragma unroll
        for (int i = 0; i < 8; i++) T += sh[i];
        int bidx = row >> 12;
        out[bidx * (N_ - 2 * SLACK) + (n - SLACK)] = T;
    }
}

// ---------------- Launch ----------------
extern "C" void kernel_launch(void* const* d_in, const int* in_sizes, int n_in,
                              void* d_out, int out_size) {
    const float* x        = (const float*)d_in[0];
    const float* W_exp    = (const float*)d_in[1];
    const float* b_exp    = (const float*)d_in[2];
    const float* pos_emb  = (const float*)d_in[3];
    const float* ln_att_g = (const float*)d_in[4];
    const float* ln_att_b = (const float*)d_in[5];
    const float* Wqkv     = (const float*)d_in[6];
    const float* Wout     = (const float*)d_in[7];
    const float* ln_ff_g  = (const float*)d_in[8];
    const float* ln_ff_b  = (const float*)d_in[9];
    const float* W1       = (const float*)d_in[10];
    const float* b1       = (const float*)d_in[11];
    const float* W2       = (const float*)d_in[12];
    const float* b2       = (const float*)d_in[13];
    const float* ln_f_g   = (const float*)d_in[14];
    const float* ln_f_b   = (const float*)d_in[15];
    const float* W_logits = (const float*)d_in[16];
    float* out = (float*)d_out;

    float *ph;
    __half *pyh, *pqkvh, *poh, *pffh;
    unsigned *pwp;
    cudaGetSymbolAddress((void**)&ph,    g_h);
    cudaGetSymbolAddress((void**)&pyh,   g_yh);
    cudaGetSymbolAddress((void**)&pqkvh, g_qkvh);
    cudaGetSymbolAddress((void**)&poh,   g_oh);
    cudaGetSymbolAddress((void**)&pffh,  g_ffh);
    cudaGetSymbolAddress((void**)&pwp,   g_wp);

    cudaFuncSetAttribute(attn_mma_kernel, cudaFuncAttributeMaxDynamicSharedMemorySize, ATTN_SMEM);
    cudaFuncSetAttribute(hgemm<0>, cudaFuncAttributeMaxDynamicSharedMemorySize, HG_SMEM);
    cudaFuncSetAttribute(hgemm<1>, cudaFuncAttributeMaxDynamicSharedMemorySize, HG_SMEM);
    cudaFuncSetAttribute(hgemm<2>, cudaFuncAttributeMaxDynamicSharedMemorySize, HG_SMEM);
    cudaFuncSetAttribute(hgemm<3>, cudaFuncAttributeMaxDynamicSharedMemorySize, HG_SMEM);

    rope_table_kernel<<<(N_ * 32 + 255) / 256, 256>>>();
    pack_w_kernel<<<(786432 + 255) / 256, 256>>>(Wqkv, pwp + WQKV_OFF, DEPTH * LD / 2, QKVW);
    pack_w_kernel<<<(262144 + 255) / 256, 256>>>(Wout, pwp + WOUT_OFF, DEPTH * INNER / 2, LD);
    pack_w_kernel<<<(524288 + 255) / 256, 256>>>(W1,   pwp + W1_OFF,   DEPTH * LD / 2, FF);
    pack_w_kernel<<<(524288 + 255) / 256, 256>>>(W2,   pwp + W2_OFF,   DEPTH * FF / 2, LD);
    expand_kernel<<<R_, LD>>>(x, W_exp, b_exp, pos_emb);

    for (int l = 0; l < DEPTH; ++l) {
        ln_kernel<<<R_, LD>>>(ph, pyh, ln_att_g + l * LD, ln_att_b + l * LD);
        hgemm<0><<<dim3(QKVW / 128, R_ / 128), 256, HG_SMEM>>>(
            pyh, pwp + WQKV_OFF + (size_t)l * (LD / 2) * QKVW, pqkvh, nullptr, QKVW, LD);
        attn_mma_kernel<<<dim3(N_ / WW, H_, B_), 256, ATTN_SMEM>>>(pqkvh, poh);
        hgemm<2><<<dim3(LD / 128, R_ / 128), 256, HG_SMEM>>>(
            poh, pwp + WOUT_OFF + (size_t)l * (INNER / 2) * LD, ph, nullptr, LD, INNER);
        ln_kernel<<<R_, LD>>>(ph, pyh, ln_ff_g + l * LD, ln_ff_b + l * LD);
        hgemm<1><<<dim3(FF / 128, R_ / 128), 256, HG_SMEM>>>(
            pyh, pwp + W1_OFF + (size_t)l * (LD / 2) * FF, pffh, b1 + (size_t)l * FF, FF, LD);
        hgemm<3><<<dim3(LD / 128, R_ / 128), 256, HG_SMEM>>>(
            pffh, pwp + W2_OFF + (size_t)l * (FF / 2) * LD, ph, b2 + (size_t)l * LD, LD, FF);
    }

    final_kernel<<<R_, LD>>>(ln_f_g, ln_f_b, W_logits, out);
}